// round 3
// baseline (speedup 1.0000x reference)
#include <cuda_runtime.h>

#define NN 10000
#define EE 320000
#define HCv 256
#define EDv 64
#define TOT (EE + NN)
#define FULLMASK 0xffffffffu

static __device__ __forceinline__ int clampN(int v) {
    v = v < 0 ? 0 : v;
    return v > (NN - 1) ? (NN - 1) : v;
}

// ---------------- scratch (device globals; no allocations allowed) ----------------
static __device__ float g_xl[NN * HCv];           // 10.24 MB
static __device__ float g_xr[NN * HCv];           // 10.24 MB
static __device__ float g_logits[TOT * 4];        // 5.28 MB
static __device__ float g_loop_attr[NN * EDv];    // 2.56 MB
static __device__ float g_mx[NN * 4];
static __device__ float g_den[NN * 4];
static __device__ int   g_deg[NN];
static __device__ int   g_rowptr[NN + 1];
static __device__ int   g_cursor[NN];
static __device__ int   g_eids[EE];

// ---------------- CSR build ----------------
__global__ void k_init() {
    int i = blockIdx.x * blockDim.x + threadIdx.x;
    if (i < NN) { g_deg[i] = 0; g_cursor[i] = 0; }
}

__global__ void k_count(const int* __restrict__ ei) {
    int e = blockIdx.x * blockDim.x + threadIdx.x;
    if (e < EE) atomicAdd(&g_deg[clampN(ei[EE + e])], 1);
}

__global__ void k_scan() {
    __shared__ int s[1024];
    __shared__ int carry_s;
    int t = threadIdx.x;
    if (t == 0) carry_s = 0;
    __syncthreads();
    for (int base = 0; base < NN; base += 1024) {
        int v = (base + t < NN) ? g_deg[base + t] : 0;
        s[t] = v;
        __syncthreads();
        for (int off = 1; off < 1024; off <<= 1) {
            int y = (t >= off) ? s[t - off] : 0;
            __syncthreads();
            s[t] += y;
            __syncthreads();
        }
        int carry = carry_s;
        if (base + t < NN) g_rowptr[base + t] = carry + s[t] - v;
        __syncthreads();
        if (t == 0) carry_s = carry + s[1023];
        __syncthreads();
    }
    if (t == 0) g_rowptr[NN] = carry_s;
}

__global__ void k_fill(const int* __restrict__ ei) {
    int e = blockIdx.x * blockDim.x + threadIdx.x;
    if (e < EE) {
        int d = clampN(ei[EE + e]);
        int pos = g_rowptr[d] + atomicAdd(&g_cursor[d], 1);
        if (pos >= 0 && pos < EE) g_eids[pos] = e;
    }
}

// ---------------- node projections: out[m][j] = sum_k X[m][k]*W[j][k] + b[j] ----------------
__global__ void k_proj(const float* __restrict__ X, const float* __restrict__ W,
                       const float* __restrict__ b, int which) {
    __shared__ float As[16][68];
    __shared__ float Ws[16][68];
    float* out = which ? g_xr : g_xl;
    int t  = threadIdx.x;
    int tx = t & 15, ty = t >> 4;
    int bm = blockIdx.x * 64, bj = blockIdx.y * 64;
    int lrow = t >> 2, lk = (t & 3) * 4;
    float acc[4][4] = {{0.f,0.f,0.f,0.f},{0.f,0.f,0.f,0.f},{0.f,0.f,0.f,0.f},{0.f,0.f,0.f,0.f}};
    for (int k0 = 0; k0 < 256; k0 += 16) {
        float4 av = make_float4(0.f, 0.f, 0.f, 0.f);
        int arow = bm + lrow;
        if (arow < NN) av = *(const float4*)&X[(size_t)arow * 256 + k0 + lk];
        As[lk + 0][lrow] = av.x; As[lk + 1][lrow] = av.y;
        As[lk + 2][lrow] = av.z; As[lk + 3][lrow] = av.w;
        float4 wv = *(const float4*)&W[(size_t)(bj + lrow) * 256 + k0 + lk];
        Ws[lk + 0][lrow] = wv.x; Ws[lk + 1][lrow] = wv.y;
        Ws[lk + 2][lrow] = wv.z; Ws[lk + 3][lrow] = wv.w;
        __syncthreads();
#pragma unroll
        for (int kk = 0; kk < 16; kk++) {
            float4 a4 = *(const float4*)&As[kk][ty * 4];
            float4 w4 = *(const float4*)&Ws[kk][tx * 4];
            acc[0][0] += a4.x * w4.x; acc[0][1] += a4.x * w4.y; acc[0][2] += a4.x * w4.z; acc[0][3] += a4.x * w4.w;
            acc[1][0] += a4.y * w4.x; acc[1][1] += a4.y * w4.y; acc[1][2] += a4.y * w4.z; acc[1][3] += a4.y * w4.w;
            acc[2][0] += a4.z * w4.x; acc[2][1] += a4.z * w4.y; acc[2][2] += a4.z * w4.z; acc[2][3] += a4.z * w4.w;
            acc[3][0] += a4.w * w4.x; acc[3][1] += a4.w * w4.y; acc[3][2] += a4.w * w4.z; acc[3][3] += a4.w * w4.w;
        }
        __syncthreads();
    }
#pragma unroll
    for (int i = 0; i < 4; i++) {
        int row = bm + ty * 4 + i;
        if (row < NN) {
#pragma unroll
            for (int j = 0; j < 4; j++) {
                int col = bj + tx * 4 + j;
                out[(size_t)row * 256 + col] = acc[i][j] + b[col];
            }
        }
    }
}

// ---------------- self-loop attr = mean of incoming edge_attr ----------------
__global__ void k_loopattr(const float* __restrict__ ea) {
    int w = blockIdx.x * (blockDim.x >> 5) + (threadIdx.x >> 5);
    int lane = threadIdx.x & 31;
    if (w >= NN) return;
    int start = g_rowptr[w];
    int deg = g_rowptr[w + 1] - start;
    float a0 = 0.f, a1 = 0.f;
    for (int i = 0; i < deg; i++) {
        int e = g_eids[start + i];
        a0 += ea[(size_t)e * 64 + lane];
        a1 += ea[(size_t)e * 64 + 32 + lane];
    }
    float inv = 1.0f / (float)max(deg, 1);
    g_loop_attr[w * 64 + lane] = a0 * inv;
    g_loop_attr[w * 64 + 32 + lane] = a1 * inv;
}

// ---------------- edge logits: ep = We @ ea; m = xl[src]+xr[dst]+ep; leaky; dot att ----------------
// 8 edges per warp, 8 warps per block. We^T cached in a 32x256 static-shared
// k-tile (32 KB), two tiles consumed against the a0/a1 register halves.
#define EPW 8   // edges per warp
__global__ __launch_bounds__(256) void k_logits(const int* __restrict__ ei,
                                                const float* __restrict__ eattr,
                                                const float* __restrict__ We,
                                                const float* __restrict__ att) {
    __shared__ float WeT[32 * 256];   // WeT[k][c] = We[c*64 + tile*32 + k]
    __shared__ float att_s[256];
    int t = threadIdx.x;
    att_s[t] = att[t];

    int lane = t & 31;
    int warp = t >> 5;
    long long base = (long long)(blockIdx.x * 8 + warp) * EPW;
    if (base > (long long)TOT - EPW) base = (long long)TOT - EPW;  // tail: duplicate work, identical stores
    int c0 = lane * 8;

    float a0[EPW], a1[EPW];
    int src[EPW], dst[EPW];
#pragma unroll
    for (int j = 0; j < EPW; j++) {
        long long e = base + j;
        const float* p;
        if (e < EE) {
            src[j] = clampN(ei[e]);
            dst[j] = clampN(ei[EE + e]);
            p = eattr + e * 64;
        } else {
            int n = (int)(e - EE);
            src[j] = n; dst[j] = n;
            p = g_loop_attr + (size_t)n * 64;
        }
        a0[j] = p[lane];
        a1[j] = p[lane + 32];
    }

    float ep[EPW][8];
#pragma unroll
    for (int j = 0; j < EPW; j++)
#pragma unroll
        for (int q = 0; q < 8; q++) ep[j][q] = 0.f;

#pragma unroll
    for (int tile = 0; tile < 2; tile++) {
        __syncthreads();
        for (int i = t; i < 32 * 256; i += 256) {
            int k = i >> 8, c = i & 255;
            WeT[k * 256 + c] = We[c * 64 + tile * 32 + k];
        }
        __syncthreads();
#pragma unroll 4
        for (int k = 0; k < 32; k++) {
            float4 w0 = *(const float4*)&WeT[k * 256 + c0];
            float4 w1 = *(const float4*)&WeT[k * 256 + c0 + 4];
#pragma unroll
            for (int j = 0; j < EPW; j++) {
                float av = __shfl_sync(FULLMASK, tile ? a1[j] : a0[j], k);
                ep[j][0] = fmaf(w0.x, av, ep[j][0]); ep[j][1] = fmaf(w0.y, av, ep[j][1]);
                ep[j][2] = fmaf(w0.z, av, ep[j][2]); ep[j][3] = fmaf(w0.w, av, ep[j][3]);
                ep[j][4] = fmaf(w1.x, av, ep[j][4]); ep[j][5] = fmaf(w1.y, av, ep[j][5]);
                ep[j][6] = fmaf(w1.z, av, ep[j][6]); ep[j][7] = fmaf(w1.w, av, ep[j][7]);
            }
        }
    }

    int head = lane >> 3;
#pragma unroll
    for (int j = 0; j < EPW; j++) {
        const float4* xlp = (const float4*)(g_xl + (size_t)src[j] * 256 + c0);
        const float4* xrp = (const float4*)(g_xr + (size_t)dst[j] * 256 + c0);
        float4 xa = xlp[0], xb = xlp[1];
        float4 ra = xrp[0], rb = xrp[1];
        float m[8];
        m[0] = ep[j][0] + xa.x + ra.x; m[1] = ep[j][1] + xa.y + ra.y;
        m[2] = ep[j][2] + xa.z + ra.z; m[3] = ep[j][3] + xa.w + ra.w;
        m[4] = ep[j][4] + xb.x + rb.x; m[5] = ep[j][5] + xb.y + rb.y;
        m[6] = ep[j][6] + xb.z + rb.z; m[7] = ep[j][7] + xb.w + rb.w;
        float s = 0.f;
#pragma unroll
        for (int q = 0; q < 8; q++) {
            float mv = m[q];
            mv = (mv >= 0.f) ? mv : 0.2f * mv;
            s = fmaf(mv, att_s[c0 + q], s);
        }
        s += __shfl_down_sync(FULLMASK, s, 4);
        s += __shfl_down_sync(FULLMASK, s, 2);
        s += __shfl_down_sync(FULLMASK, s, 1);
        if ((lane & 7) == 0)
            g_logits[(base + j) * 4 + head] = s;
    }
}

// ---------------- per-node softmax + aggregation + SiLU + LayerNorm ----------------
__global__ void k_node(const int* __restrict__ ei, const float* __restrict__ bias,
                       const float* __restrict__ gamma, const float* __restrict__ beta,
                       float* __restrict__ out_h) {
    __shared__ float red[256];
    __shared__ float s_mx[4];
    __shared__ float s_inv[4];
    __shared__ float s_alpha[64 * 4];
    __shared__ int   s_srcs[64];
    __shared__ float s_mu, s_var;
    int n = blockIdx.x, t = threadIdx.x;
    int start = g_rowptr[n];
    int deg = g_rowptr[n + 1] - start;
    int cnt = deg + 1;
    int h4 = t & 3;

    float lm = -1e30f;
    for (int i = t >> 2; i < cnt; i += 64) {
        int e = (i < deg) ? g_eids[start + i] : (EE + n);
        lm = fmaxf(lm, g_logits[(size_t)e * 4 + h4]);
    }
    red[t] = lm;
    __syncthreads();
    if (t < 4) {
        float m = -1e30f;
        for (int j = t; j < 256; j += 4) m = fmaxf(m, red[j]);
        s_mx[t] = m;
    }
    __syncthreads();
    float mxh = s_mx[h4];
    float ls = 0.f;
    for (int i = t >> 2; i < cnt; i += 64) {
        int e = (i < deg) ? g_eids[start + i] : (EE + n);
        ls += __expf(g_logits[(size_t)e * 4 + h4] - mxh);
    }
    red[t] = ls;
    __syncthreads();
    if (t < 4) {
        float sum = 0.f;
        for (int j = t; j < 256; j += 4) sum += red[j];
        g_den[n * 4 + t] = sum;
        g_mx[n * 4 + t] = s_mx[t];
        s_inv[t] = 1.0f / sum;
    }
    __syncthreads();

    int c = t, hh = c >> 6;
    float acc = 0.f;
    for (int bb = 0; bb < cnt; bb += 64) {
        int m = min(64, cnt - bb);
        __syncthreads();
        if (t < m) {
            int i = bb + t;
            int e = (i < deg) ? g_eids[start + i] : (EE + n);
            s_srcs[t] = (e < EE) ? clampN(ei[e]) : n;
            float4 lg = *(const float4*)&g_logits[(size_t)e * 4];
            s_alpha[t * 4 + 0] = __expf(lg.x - s_mx[0]) * s_inv[0];
            s_alpha[t * 4 + 1] = __expf(lg.y - s_mx[1]) * s_inv[1];
            s_alpha[t * 4 + 2] = __expf(lg.z - s_mx[2]) * s_inv[2];
            s_alpha[t * 4 + 3] = __expf(lg.w - s_mx[3]) * s_inv[3];
        }
        __syncthreads();
        for (int i = 0; i < m; i++)
            acc = fmaf(s_alpha[i * 4 + hh], g_xl[(size_t)s_srcs[i] * 256 + c], acc);
    }

    float v = acc + bias[c];
    v = v / (1.0f + __expf(-v));   // SiLU
    __syncthreads();
    red[t] = v;
    __syncthreads();
    for (int s = 128; s > 0; s >>= 1) { if (t < s) red[t] += red[t + s]; __syncthreads(); }
    if (t == 0) s_mu = red[0] * (1.0f / 256.0f);
    __syncthreads();
    float d = v - s_mu;
    red[t] = d * d;
    __syncthreads();
    for (int s = 128; s > 0; s >>= 1) { if (t < s) red[t] += red[t + s]; __syncthreads(); }
    if (t == 0) s_var = red[0] * (1.0f / 256.0f);
    __syncthreads();
    out_h[(size_t)n * 256 + c] = d * rsqrtf(s_var + 1e-5f) * gamma[c] + beta[c];
}

// ---------------- alpha writeback ----------------
__global__ void k_alpha(const int* __restrict__ ei, float* __restrict__ out_alpha) {
    long long id = (long long)blockIdx.x * blockDim.x + threadIdx.x;
    if (id >= (long long)TOT * 4) return;
    long long e = id >> 2;
    int h = (int)(id & 3);
    int dn = (e < EE) ? clampN(ei[EE + e]) : (int)(e - EE);
    out_alpha[id] = __expf(g_logits[id] - g_mx[dn * 4 + h]) / g_den[dn * 4 + h];
}

// ---------------- launch (kernel launches ONLY — graph-capturable) ----------------
extern "C" void kernel_launch(void* const* d_in, const int* in_sizes, int n_in,
                              void* d_out, int out_size) {
    const float* x     = (const float*)d_in[0];
    const int*   ei    = (const int*)d_in[1];     // int32: JAX x64-disabled downcasts int64
    const float* eattr = (const float*)d_in[2];
    const float* Wl    = (const float*)d_in[3];
    const float* bl    = (const float*)d_in[4];
    const float* Wr    = (const float*)d_in[5];
    const float* br    = (const float*)d_in[6];
    const float* We    = (const float*)d_in[7];
    const float* att   = (const float*)d_in[8];
    const float* bias  = (const float*)d_in[9];
    const float* gamma = (const float*)d_in[10];
    const float* beta  = (const float*)d_in[11];

    float* out_h = (float*)d_out;
    float* out_alpha = out_h + (size_t)NN * HCv;

    k_init<<<(NN + 255) / 256, 256>>>();
    k_count<<<(EE + 255) / 256, 256>>>(ei);
    k_scan<<<1, 1024>>>();
    k_fill<<<(EE + 255) / 256, 256>>>(ei);

    dim3 pg((NN + 63) / 64, 4);
    k_proj<<<pg, 256>>>(x, Wl, bl, 0);
    k_proj<<<pg, 256>>>(x, Wr, br, 1);

    k_loopattr<<<(NN + 7) / 8, 256>>>(eattr);

    int nwarps = (TOT + EPW - 1) / EPW;    // 8 edges per warp
    int nblocks = (nwarps + 7) / 8;        // 8 warps per block
    k_logits<<<nblocks, 256>>>(ei, eattr, We, att);

    k_node<<<NN, 256>>>(ei, bias, gamma, beta, out_h);

    long long na = (long long)TOT * 4;
    k_alpha<<<(int)((na + 255) / 256), 256>>>(ei, out_alpha);
}

// round 4
// speedup vs baseline: 1.2665x; 1.2665x over previous
#include <cuda_runtime.h>
#include <cstdint>

#define NN 10000
#define EE 320000
#define HCv 256
#define EDv 64
#define TOT (EE + NN)
#define FULLMASK 0xffffffffu

static __device__ __forceinline__ int clampN(int v) {
    v = v < 0 ? 0 : v;
    return v > (NN - 1) ? (NN - 1) : v;
}

static __device__ __forceinline__ uint32_t f2tf32(float x) {
    uint32_t r;
    asm("cvt.rna.tf32.f32 %0, %1;" : "=r"(r) : "f"(x));
    return r;
}

// ---------------- scratch (device globals; no allocations allowed) ----------------
static __device__ float g_xl[NN * HCv];           // 10.24 MB
static __device__ float g_xr[NN * HCv];           // 10.24 MB
static __device__ float g_logits[TOT * 4];        // 5.28 MB
static __device__ float g_loop_attr[NN * EDv];    // 2.56 MB
static __device__ float g_WeT_hi[EDv * HCv];      // 64x256 (k-major)
static __device__ float g_WeT_lo[EDv * HCv];
static __device__ float g_mx[NN * 4];
static __device__ float g_den[NN * 4];
static __device__ int   g_deg[NN];
static __device__ int   g_rowptr[NN + 1];
static __device__ int   g_cursor[NN];
static __device__ int   g_eids[EE];

// ---------------- CSR build ----------------
__global__ void k_init() {
    int i = blockIdx.x * blockDim.x + threadIdx.x;
    if (i < NN) { g_deg[i] = 0; g_cursor[i] = 0; }
}

__global__ void k_count(const int* __restrict__ ei) {
    int e = blockIdx.x * blockDim.x + threadIdx.x;
    if (e < EE) atomicAdd(&g_deg[clampN(ei[EE + e])], 1);
}

__global__ void k_scan() {
    __shared__ int s[1024];
    __shared__ int carry_s;
    int t = threadIdx.x;
    if (t == 0) carry_s = 0;
    __syncthreads();
    for (int base = 0; base < NN; base += 1024) {
        int v = (base + t < NN) ? g_deg[base + t] : 0;
        s[t] = v;
        __syncthreads();
        for (int off = 1; off < 1024; off <<= 1) {
            int y = (t >= off) ? s[t - off] : 0;
            __syncthreads();
            s[t] += y;
            __syncthreads();
        }
        int carry = carry_s;
        if (base + t < NN) g_rowptr[base + t] = carry + s[t] - v;
        __syncthreads();
        if (t == 0) carry_s = carry + s[1023];
        __syncthreads();
    }
    if (t == 0) g_rowptr[NN] = carry_s;
}

__global__ void k_fill(const int* __restrict__ ei) {
    int e = blockIdx.x * blockDim.x + threadIdx.x;
    if (e < EE) {
        int d = clampN(ei[EE + e]);
        int pos = g_rowptr[d] + atomicAdd(&g_cursor[d], 1);
        if (pos >= 0 && pos < EE) g_eids[pos] = e;
    }
}

// ---------------- We split into tf32 hi/lo, k-major ----------------
__global__ void k_prep_we(const float* __restrict__ We) {
    int i = blockIdx.x * blockDim.x + threadIdx.x;   // over 64*256
    if (i >= EDv * HCv) return;
    int c = i >> 6, k = i & 63;
    float v = We[i];                                  // We[c][k]
    uint32_t hb = f2tf32(v);
    float hf = __uint_as_float(hb);
    float lo = v - hf;
    uint32_t lb = f2tf32(lo);
    g_WeT_hi[k * 256 + c] = hf;
    g_WeT_lo[k * 256 + c] = __uint_as_float(lb);
}

// ---------------- node projections (FFMA tiled) ----------------
__global__ void k_proj(const float* __restrict__ X, const float* __restrict__ W,
                       const float* __restrict__ b, int which) {
    __shared__ float As[16][68];
    __shared__ float Ws[16][68];
    float* out = which ? g_xr : g_xl;
    int t  = threadIdx.x;
    int tx = t & 15, ty = t >> 4;
    int bm = blockIdx.x * 64, bj = blockIdx.y * 64;
    int lrow = t >> 2, lk = (t & 3) * 4;
    float acc[4][4] = {{0.f,0.f,0.f,0.f},{0.f,0.f,0.f,0.f},{0.f,0.f,0.f,0.f},{0.f,0.f,0.f,0.f}};
    for (int k0 = 0; k0 < 256; k0 += 16) {
        float4 av = make_float4(0.f, 0.f, 0.f, 0.f);
        int arow = bm + lrow;
        if (arow < NN) av = *(const float4*)&X[(size_t)arow * 256 + k0 + lk];
        As[lk + 0][lrow] = av.x; As[lk + 1][lrow] = av.y;
        As[lk + 2][lrow] = av.z; As[lk + 3][lrow] = av.w;
        float4 wv = *(const float4*)&W[(size_t)(bj + lrow) * 256 + k0 + lk];
        Ws[lk + 0][lrow] = wv.x; Ws[lk + 1][lrow] = wv.y;
        Ws[lk + 2][lrow] = wv.z; Ws[lk + 3][lrow] = wv.w;
        __syncthreads();
#pragma unroll
        for (int kk = 0; kk < 16; kk++) {
            float4 a4 = *(const float4*)&As[kk][ty * 4];
            float4 w4 = *(const float4*)&Ws[kk][tx * 4];
            acc[0][0] += a4.x * w4.x; acc[0][1] += a4.x * w4.y; acc[0][2] += a4.x * w4.z; acc[0][3] += a4.x * w4.w;
            acc[1][0] += a4.y * w4.x; acc[1][1] += a4.y * w4.y; acc[1][2] += a4.y * w4.z; acc[1][3] += a4.y * w4.w;
            acc[2][0] += a4.z * w4.x; acc[2][1] += a4.z * w4.y; acc[2][2] += a4.z * w4.z; acc[2][3] += a4.z * w4.w;
            acc[3][0] += a4.w * w4.x; acc[3][1] += a4.w * w4.y; acc[3][2] += a4.w * w4.z; acc[3][3] += a4.w * w4.w;
        }
        __syncthreads();
    }
#pragma unroll
    for (int i = 0; i < 4; i++) {
        int row = bm + ty * 4 + i;
        if (row < NN) {
#pragma unroll
            for (int j = 0; j < 4; j++) {
                int col = bj + tx * 4 + j;
                out[(size_t)row * 256 + col] = acc[i][j] + b[col];
            }
        }
    }
}

// ---------------- self-loop attr = mean of incoming edge_attr ----------------
__global__ void k_loopattr(const float* __restrict__ ea) {
    int w = blockIdx.x * (blockDim.x >> 5) + (threadIdx.x >> 5);
    int lane = threadIdx.x & 31;
    if (w >= NN) return;
    int start = g_rowptr[w];
    int deg = g_rowptr[w + 1] - start;
    float a0 = 0.f, a1 = 0.f;
    for (int i = 0; i < deg; i++) {
        int e = g_eids[start + i];
        a0 += ea[(size_t)e * 64 + lane];
        a1 += ea[(size_t)e * 64 + 32 + lane];
    }
    float inv = 1.0f / (float)max(deg, 1);
    g_loop_attr[w * 64 + lane] = a0 * inv;
    g_loop_attr[w * 64 + 32 + lane] = a1 * inv;
}

// ---------------- edge logits via split-tf32 mma ----------------
// Block: 32 edges, 256 threads (8 warps: 2 M-tiles x 4 N-groups of 32 cols).
// EP = EA(32x64) @ WeT(64x256) by N-halves of 128; 3-mma split-tf32.
#define EAS 72    // EA_s row stride (floats)
#define BS 136    // B_s row stride
#define EPS 136   // EP_s row stride

__global__ __launch_bounds__(256) void k_logits_mma(const int* __restrict__ ei,
                                                    const float* __restrict__ eattr,
                                                    const float* __restrict__ att) {
    __shared__ float EA_s[32 * EAS];       // 9.0 KB raw fp32 edge attrs
    __shared__ float B_hi[8 * BS];         // 4.25 KB
    __shared__ float B_lo[8 * BS];
    __shared__ float EP_s[32 * EPS];       // 17 KB (one N-half of EP)
    __shared__ float att_s[256];
    __shared__ int   s_src[32], s_dst[32];

    int t = threadIdx.x;
    int lane = t & 31;
    int warp = t >> 5;
    int mt = warp >> 2;          // M-tile (0..1), 16 edges each
    int ng = warp & 3;           // N-group (0..3), 32 cols of the 128-half

    att_s[t] = att[t];

    int base = blockIdx.x * 32;
    if (base > TOT - 32) base = TOT - 32;   // tail overlap: identical stores

    if (t < 32) {
        int e = base + t;
        int s, d;
        if (e < EE) { s = clampN(ei[e]); d = clampN(ei[EE + e]); }
        else { s = e - EE; d = e - EE; }
        s_src[t] = s; s_dst[t] = d;
    }
    // stage edge attrs: 8 threads per edge, 8 floats each
    {
        int el = t >> 3, part = t & 7;
        int e = base + el;
        const float* p = (e < EE) ? (eattr + (size_t)e * 64) : (g_loop_attr + (size_t)(e - EE) * 64);
        float4 v0 = *(const float4*)&p[part * 8];
        float4 v1 = *(const float4*)&p[part * 8 + 4];
        float* q = &EA_s[el * EAS + part * 8];
        *(float4*)q = v0;
        *(float4*)(q + 4) = v1;
    }
    __syncthreads();

    int grp = lane >> 2;     // 0..7
    int thr = lane & 3;      // 0..3
    int row0 = mt * 16 + grp;

#pragma unroll
    for (int half = 0; half < 2; half++) {
        float acc[4][4];
#pragma unroll
        for (int nt = 0; nt < 4; nt++)
#pragma unroll
            for (int q = 0; q < 4; q++) acc[nt][q] = 0.f;

        for (int kc = 0; kc < 8; kc++) {
            __syncthreads();
            // stage B k-chunk: 8 k-rows x 128 cols (hi & lo)
#pragma unroll
            for (int r = 0; r < 4; r++) {
                int i = t + r * 256;
                int kk = i >> 7, c = i & 127;
                int gidx = (kc * 8 + kk) * 256 + half * 128 + c;
                B_hi[kk * BS + c] = g_WeT_hi[gidx];
                B_lo[kk * BS + c] = g_WeT_lo[gidx];
            }
            __syncthreads();

            // A fragment for this warp's 16-edge tile
            float a0 = EA_s[row0 * EAS + kc * 8 + thr];
            float a1 = EA_s[(row0 + 8) * EAS + kc * 8 + thr];
            float a2 = EA_s[row0 * EAS + kc * 8 + thr + 4];
            float a3 = EA_s[(row0 + 8) * EAS + kc * 8 + thr + 4];
            uint32_t ah0 = f2tf32(a0), ah1 = f2tf32(a1), ah2 = f2tf32(a2), ah3 = f2tf32(a3);
            uint32_t al0 = f2tf32(a0 - __uint_as_float(ah0));
            uint32_t al1 = f2tf32(a1 - __uint_as_float(ah1));
            uint32_t al2 = f2tf32(a2 - __uint_as_float(ah2));
            uint32_t al3 = f2tf32(a3 - __uint_as_float(ah3));

#pragma unroll
            for (int nt = 0; nt < 4; nt++) {
                int ccol = (ng * 4 + nt) * 8 + grp;
                uint32_t bh0 = __float_as_uint(B_hi[thr * BS + ccol]);
                uint32_t bh1 = __float_as_uint(B_hi[(thr + 4) * BS + ccol]);
                uint32_t bl0 = __float_as_uint(B_lo[thr * BS + ccol]);
                uint32_t bl1 = __float_as_uint(B_lo[(thr + 4) * BS + ccol]);
                asm("mma.sync.aligned.m16n8k8.row.col.f32.tf32.tf32.f32 "
                    "{%0,%1,%2,%3}, {%4,%5,%6,%7}, {%8,%9}, {%0,%1,%2,%3};"
                    : "+f"(acc[nt][0]), "+f"(acc[nt][1]), "+f"(acc[nt][2]), "+f"(acc[nt][3])
                    : "r"(al0), "r"(al1), "r"(al2), "r"(al3), "r"(bh0), "r"(bh1));
                asm("mma.sync.aligned.m16n8k8.row.col.f32.tf32.tf32.f32 "
                    "{%0,%1,%2,%3}, {%4,%5,%6,%7}, {%8,%9}, {%0,%1,%2,%3};"
                    : "+f"(acc[nt][0]), "+f"(acc[nt][1]), "+f"(acc[nt][2]), "+f"(acc[nt][3])
                    : "r"(ah0), "r"(ah1), "r"(ah2), "r"(ah3), "r"(bl0), "r"(bl1));
                asm("mma.sync.aligned.m16n8k8.row.col.f32.tf32.tf32.f32 "
                    "{%0,%1,%2,%3}, {%4,%5,%6,%7}, {%8,%9}, {%0,%1,%2,%3};"
                    : "+f"(acc[nt][0]), "+f"(acc[nt][1]), "+f"(acc[nt][2]), "+f"(acc[nt][3])
                    : "r"(ah0), "r"(ah1), "r"(ah2), "r"(ah3), "r"(bh0), "r"(bh1));
            }
        }

        // dump EP fragments to smem
        __syncthreads();
#pragma unroll
        for (int nt = 0; nt < 4; nt++) {
            int cb = (ng * 4 + nt) * 8 + 2 * thr;
            EP_s[row0 * EPS + cb]           = acc[nt][0];
            EP_s[row0 * EPS + cb + 1]       = acc[nt][1];
            EP_s[(row0 + 8) * EPS + cb]     = acc[nt][2];
            EP_s[(row0 + 8) * EPS + cb + 1] = acc[nt][3];
        }
        __syncthreads();

        // epilogue: 8 threads per edge, 16 cols each (within one head)
        {
            int el = t >> 3, sub = t & 7;
            int c0 = sub * 16;
            int hl = sub >> 2;                      // head within half
            int src = s_src[el], dst = s_dst[el];
            const float* xlp = g_xl + (size_t)src * 256 + half * 128 + c0;
            const float* xrp = g_xr + (size_t)dst * 256 + half * 128 + c0;
            const float* epp = &EP_s[el * EPS + c0];
            const float* ats = &att_s[half * 128 + c0];
            float s = 0.f;
#pragma unroll
            for (int q4 = 0; q4 < 4; q4++) {
                float4 ev = *(const float4*)&epp[q4 * 4];
                float4 lv = *(const float4*)&xlp[q4 * 4];
                float4 rv = *(const float4*)&xrp[q4 * 4];
                float4 av = *(const float4*)&ats[q4 * 4];
                float m0 = ev.x + lv.x + rv.x; m0 = (m0 >= 0.f) ? m0 : 0.2f * m0;
                float m1 = ev.y + lv.y + rv.y; m1 = (m1 >= 0.f) ? m1 : 0.2f * m1;
                float m2 = ev.z + lv.z + rv.z; m2 = (m2 >= 0.f) ? m2 : 0.2f * m2;
                float m3 = ev.w + lv.w + rv.w; m3 = (m3 >= 0.f) ? m3 : 0.2f * m3;
                s = fmaf(m0, av.x, s); s = fmaf(m1, av.y, s);
                s = fmaf(m2, av.z, s); s = fmaf(m3, av.w, s);
            }
            s += __shfl_xor_sync(FULLMASK, s, 1);
            s += __shfl_xor_sync(FULLMASK, s, 2);
            if ((t & 3) == 0)
                g_logits[(size_t)(base + el) * 4 + half * 2 + hl] = s;
        }
    }
}

// ---------------- per-node softmax + aggregation + SiLU + LayerNorm ----------------
__global__ void k_node(const int* __restrict__ ei, const float* __restrict__ bias,
                       const float* __restrict__ gamma, const float* __restrict__ beta,
                       float* __restrict__ out_h) {
    __shared__ float red[256];
    __shared__ float s_mx[4];
    __shared__ float s_inv[4];
    __shared__ float s_alpha[64 * 4];
    __shared__ int   s_srcs[64];
    __shared__ float s_mu, s_var;
    int n = blockIdx.x, t = threadIdx.x;
    int start = g_rowptr[n];
    int deg = g_rowptr[n + 1] - start;
    int cnt = deg + 1;
    int h4 = t & 3;

    float lm = -1e30f;
    for (int i = t >> 2; i < cnt; i += 64) {
        int e = (i < deg) ? g_eids[start + i] : (EE + n);
        lm = fmaxf(lm, g_logits[(size_t)e * 4 + h4]);
    }
    red[t] = lm;
    __syncthreads();
    if (t < 4) {
        float m = -1e30f;
        for (int j = t; j < 256; j += 4) m = fmaxf(m, red[j]);
        s_mx[t] = m;
    }
    __syncthreads();
    float mxh = s_mx[h4];
    float ls = 0.f;
    for (int i = t >> 2; i < cnt; i += 64) {
        int e = (i < deg) ? g_eids[start + i] : (EE + n);
        ls += __expf(g_logits[(size_t)e * 4 + h4] - mxh);
    }
    red[t] = ls;
    __syncthreads();
    if (t < 4) {
        float sum = 0.f;
        for (int j = t; j < 256; j += 4) sum += red[j];
        g_den[n * 4 + t] = sum;
        g_mx[n * 4 + t] = s_mx[t];
        s_inv[t] = 1.0f / sum;
    }
    __syncthreads();

    int c = t, hh = c >> 6;
    float acc = 0.f;
    for (int bb = 0; bb < cnt; bb += 64) {
        int m = min(64, cnt - bb);
        __syncthreads();
        if (t < m) {
            int i = bb + t;
            int e = (i < deg) ? g_eids[start + i] : (EE + n);
            s_srcs[t] = (e < EE) ? clampN(ei[e]) : n;
            float4 lg = *(const float4*)&g_logits[(size_t)e * 4];
            s_alpha[t * 4 + 0] = __expf(lg.x - s_mx[0]) * s_inv[0];
            s_alpha[t * 4 + 1] = __expf(lg.y - s_mx[1]) * s_inv[1];
            s_alpha[t * 4 + 2] = __expf(lg.z - s_mx[2]) * s_inv[2];
            s_alpha[t * 4 + 3] = __expf(lg.w - s_mx[3]) * s_inv[3];
        }
        __syncthreads();
        for (int i = 0; i < m; i++)
            acc = fmaf(s_alpha[i * 4 + hh], g_xl[(size_t)s_srcs[i] * 256 + c], acc);
    }

    float v = acc + bias[c];
    v = v / (1.0f + __expf(-v));   // SiLU
    __syncthreads();
    red[t] = v;
    __syncthreads();
    for (int s = 128; s > 0; s >>= 1) { if (t < s) red[t] += red[t + s]; __syncthreads(); }
    if (t == 0) s_mu = red[0] * (1.0f / 256.0f);
    __syncthreads();
    float d = v - s_mu;
    red[t] = d * d;
    __syncthreads();
    for (int s = 128; s > 0; s >>= 1) { if (t < s) red[t] += red[t + s]; __syncthreads(); }
    if (t == 0) s_var = red[0] * (1.0f / 256.0f);
    __syncthreads();
    out_h[(size_t)n * 256 + c] = d * rsqrtf(s_var + 1e-5f) * gamma[c] + beta[c];
}

// ---------------- alpha writeback ----------------
__global__ void k_alpha(const int* __restrict__ ei, float* __restrict__ out_alpha) {
    long long id = (long long)blockIdx.x * blockDim.x + threadIdx.x;
    if (id >= (long long)TOT * 4) return;
    long long e = id >> 2;
    int h = (int)(id & 3);
    int dn = (e < EE) ? clampN(ei[EE + e]) : (int)(e - EE);
    out_alpha[id] = __expf(g_logits[id] - g_mx[dn * 4 + h]) / g_den[dn * 4 + h];
}

// ---------------- launch (kernel launches ONLY — graph-capturable) ----------------
extern "C" void kernel_launch(void* const* d_in, const int* in_sizes, int n_in,
                              void* d_out, int out_size) {
    const float* x     = (const float*)d_in[0];
    const int*   ei    = (const int*)d_in[1];     // int32 (JAX x64-disabled)
    const float* eattr = (const float*)d_in[2];
    const float* Wl    = (const float*)d_in[3];
    const float* bl    = (const float*)d_in[4];
    const float* Wr    = (const float*)d_in[5];
    const float* br    = (const float*)d_in[6];
    const float* We    = (const float*)d_in[7];
    const float* att   = (const float*)d_in[8];
    const float* bias  = (const float*)d_in[9];
    const float* gamma = (const float*)d_in[10];
    const float* beta  = (const float*)d_in[11];

    float* out_h = (float*)d_out;
    float* out_alpha = out_h + (size_t)NN * HCv;

    k_init<<<(NN + 255) / 256, 256>>>();
    k_count<<<(EE + 255) / 256, 256>>>(ei);
    k_scan<<<1, 1024>>>();
    k_fill<<<(EE + 255) / 256, 256>>>(ei);

    k_prep_we<<<(EDv * HCv + 255) / 256, 256>>>(We);

    dim3 pg((NN + 63) / 64, 4);
    k_proj<<<pg, 256>>>(x, Wl, bl, 0);
    k_proj<<<pg, 256>>>(x, Wr, br, 1);

    k_loopattr<<<(NN + 7) / 8, 256>>>(eattr);

    k_logits_mma<<<(TOT + 31) / 32, 256>>>(ei, eattr, att);

    k_node<<<NN, 256>>>(ei, bias, gamma, beta, out_h);

    long long na = (long long)TOT * 4;
    k_alpha<<<(int)((na + 255) / 256), 256>>>(ei, out_alpha);
}

// round 5
// speedup vs baseline: 1.4269x; 1.1266x over previous
#include <cuda_runtime.h>
#include <cstdint>

#define NN 10000
#define EE 320000
#define HCv 256
#define EDv 64
#define TOT (EE + NN)
#define FULLMASK 0xffffffffu

static __device__ __forceinline__ int clampN(int v) {
    v = v < 0 ? 0 : v;
    return v > (NN - 1) ? (NN - 1) : v;
}

static __device__ __forceinline__ uint32_t f2tf32(float x) {
    uint32_t r;
    asm("cvt.rna.tf32.f32 %0, %1;" : "=r"(r) : "f"(x));
    return r;
}

// ---------------- scratch (device globals; no allocations allowed) ----------------
static __device__ float g_xl[NN * HCv];
static __device__ float g_xr[NN * HCv];
static __device__ float g_logits[TOT * 4];
static __device__ float g_loop_attr[NN * EDv];
static __device__ float g_WeT_hi[EDv * HCv];      // k-major [64][256]
static __device__ float g_WeT_lo[EDv * HCv];
static __device__ float g_mx[NN * 4];
static __device__ float g_den[NN * 4];
static __device__ int   g_deg[NN];
static __device__ int   g_rowptr[NN + 1];
static __device__ int   g_cursor[NN];
static __device__ int   g_eids[EE];

// ---------------- CSR build ----------------
__global__ void k_init() {
    int i = blockIdx.x * blockDim.x + threadIdx.x;
    if (i < NN) { g_deg[i] = 0; g_cursor[i] = 0; }
}

__global__ void k_count(const int* __restrict__ ei) {
    int e = blockIdx.x * blockDim.x + threadIdx.x;
    if (e < EE) atomicAdd(&g_deg[clampN(ei[EE + e])], 1);
}

__global__ void k_scan() {
    __shared__ int s[1024];
    __shared__ int carry_s;
    int t = threadIdx.x;
    if (t == 0) carry_s = 0;
    __syncthreads();
    for (int base = 0; base < NN; base += 1024) {
        int v = (base + t < NN) ? g_deg[base + t] : 0;
        s[t] = v;
        __syncthreads();
        for (int off = 1; off < 1024; off <<= 1) {
            int y = (t >= off) ? s[t - off] : 0;
            __syncthreads();
            s[t] += y;
            __syncthreads();
        }
        int carry = carry_s;
        if (base + t < NN) g_rowptr[base + t] = carry + s[t] - v;
        __syncthreads();
        if (t == 0) carry_s = carry + s[1023];
        __syncthreads();
    }
    if (t == 0) g_rowptr[NN] = carry_s;
}

__global__ void k_fill(const int* __restrict__ ei) {
    int e = blockIdx.x * blockDim.x + threadIdx.x;
    if (e < EE) {
        int d = clampN(ei[EE + e]);
        int pos = g_rowptr[d] + atomicAdd(&g_cursor[d], 1);
        if (pos >= 0 && pos < EE) g_eids[pos] = e;
    }
}

// ---------------- We split into tf32 hi/lo, k-major ----------------
__global__ void k_prep_we(const float* __restrict__ We) {
    int i = blockIdx.x * blockDim.x + threadIdx.x;
    if (i >= EDv * HCv) return;
    int c = i >> 6, k = i & 63;
    float v = We[i];
    uint32_t hb = f2tf32(v);
    float hf = __uint_as_float(hb);
    float lo = v - hf;
    uint32_t lb = f2tf32(lo);
    g_WeT_hi[k * 256 + c] = hf;
    g_WeT_lo[k * 256 + c] = __uint_as_float(lb);
}

// ---------------- fused node projections: xl and xr in one pass over X ----------------
__global__ void k_proj2(const float* __restrict__ X, const float* __restrict__ Wl,
                        const float* __restrict__ bl, const float* __restrict__ Wr,
                        const float* __restrict__ br) {
    __shared__ float As[16][68];
    __shared__ float Wls[16][68];
    __shared__ float Wrs[16][68];
    int t  = threadIdx.x;
    int tx = t & 15, ty = t >> 4;
    int bm = blockIdx.x * 64, bj = blockIdx.y * 64;
    int lrow = t >> 2, lk = (t & 3) * 4;
    float accl[4][4] = {{0.f,0.f,0.f,0.f},{0.f,0.f,0.f,0.f},{0.f,0.f,0.f,0.f},{0.f,0.f,0.f,0.f}};
    float accr[4][4] = {{0.f,0.f,0.f,0.f},{0.f,0.f,0.f,0.f},{0.f,0.f,0.f,0.f},{0.f,0.f,0.f,0.f}};
    for (int k0 = 0; k0 < 256; k0 += 16) {
        float4 av = make_float4(0.f, 0.f, 0.f, 0.f);
        int arow = bm + lrow;
        if (arow < NN) av = *(const float4*)&X[(size_t)arow * 256 + k0 + lk];
        As[lk + 0][lrow] = av.x; As[lk + 1][lrow] = av.y;
        As[lk + 2][lrow] = av.z; As[lk + 3][lrow] = av.w;
        float4 wv = *(const float4*)&Wl[(size_t)(bj + lrow) * 256 + k0 + lk];
        Wls[lk + 0][lrow] = wv.x; Wls[lk + 1][lrow] = wv.y;
        Wls[lk + 2][lrow] = wv.z; Wls[lk + 3][lrow] = wv.w;
        float4 uv = *(const float4*)&Wr[(size_t)(bj + lrow) * 256 + k0 + lk];
        Wrs[lk + 0][lrow] = uv.x; Wrs[lk + 1][lrow] = uv.y;
        Wrs[lk + 2][lrow] = uv.z; Wrs[lk + 3][lrow] = uv.w;
        __syncthreads();
#pragma unroll
        for (int kk = 0; kk < 16; kk++) {
            float4 a4 = *(const float4*)&As[kk][ty * 4];
            float4 w4 = *(const float4*)&Wls[kk][tx * 4];
            float4 u4 = *(const float4*)&Wrs[kk][tx * 4];
            accl[0][0] += a4.x * w4.x; accl[0][1] += a4.x * w4.y; accl[0][2] += a4.x * w4.z; accl[0][3] += a4.x * w4.w;
            accl[1][0] += a4.y * w4.x; accl[1][1] += a4.y * w4.y; accl[1][2] += a4.y * w4.z; accl[1][3] += a4.y * w4.w;
            accl[2][0] += a4.z * w4.x; accl[2][1] += a4.z * w4.y; accl[2][2] += a4.z * w4.z; accl[2][3] += a4.z * w4.w;
            accl[3][0] += a4.w * w4.x; accl[3][1] += a4.w * w4.y; accl[3][2] += a4.w * w4.z; accl[3][3] += a4.w * w4.w;
            accr[0][0] += a4.x * u4.x; accr[0][1] += a4.x * u4.y; accr[0][2] += a4.x * u4.z; accr[0][3] += a4.x * u4.w;
            accr[1][0] += a4.y * u4.x; accr[1][1] += a4.y * u4.y; accr[1][2] += a4.y * u4.z; accr[1][3] += a4.y * u4.w;
            accr[2][0] += a4.z * u4.x; accr[2][1] += a4.z * u4.y; accr[2][2] += a4.z * u4.z; accr[2][3] += a4.z * u4.w;
            accr[3][0] += a4.w * u4.x; accr[3][1] += a4.w * u4.y; accr[3][2] += a4.w * u4.z; accr[3][3] += a4.w * u4.w;
        }
        __syncthreads();
    }
#pragma unroll
    for (int i = 0; i < 4; i++) {
        int row = bm + ty * 4 + i;
        if (row < NN) {
#pragma unroll
            for (int j = 0; j < 4; j++) {
                int col = bj + tx * 4 + j;
                g_xl[(size_t)row * 256 + col] = accl[i][j] + bl[col];
                g_xr[(size_t)row * 256 + col] = accr[i][j] + br[col];
            }
        }
    }
}

// ---------------- self-loop attr = mean of incoming edge_attr ----------------
__global__ void k_loopattr(const float* __restrict__ ea) {
    int w = blockIdx.x * (blockDim.x >> 5) + (threadIdx.x >> 5);
    int lane = threadIdx.x & 31;
    if (w >= NN) return;
    int start = g_rowptr[w];
    int deg = g_rowptr[w + 1] - start;
    float a0 = 0.f, a1 = 0.f;
    for (int i = 0; i < deg; i++) {
        int e = g_eids[start + i];
        a0 += ea[(size_t)e * 64 + lane];
        a1 += ea[(size_t)e * 64 + 32 + lane];
    }
    float inv = 1.0f / (float)max(deg, 1);
    g_loop_attr[w * 64 + lane] = a0 * inv;
    g_loop_attr[w * 64 + 32 + lane] = a1 * inv;
}

// ---------------- edge logits via split-tf32 mma, 64 edges/block ----------------
// 8 warps = 4 M-tiles (16 edges) x 2 N-groups (32 cols). EP computed per
// 64-col quarter (= one head); B hi/lo staged per (quarter, kc) chunk.
#define EAS 72    // EA_s row stride
#define BS  72    // B row stride (thr*72+grp -> all 32 banks distinct)
#define EPS 68    // EP row stride

__global__ __launch_bounds__(256) void k_logits_mma(const int* __restrict__ ei,
                                                    const float* __restrict__ eattr,
                                                    const float* __restrict__ att) {
    __shared__ float EA_s[64 * EAS];       // 18.4 KB
    __shared__ float B_hi[8 * BS];         // 2.3 KB
    __shared__ float B_lo[8 * BS];
    __shared__ float EP_s[64 * EPS];       // 17.4 KB (one quarter)
    __shared__ float att_s[256];
    __shared__ int   s_src[64], s_dst[64];

    int t = threadIdx.x;
    int lane = t & 31;
    int warp = t >> 5;
    int mt = warp >> 1;          // M-tile 0..3 (16 edges each)
    int ng = warp & 1;           // N-group 0..1 (32 cols of the quarter)

    att_s[t] = att[t];

    int base = blockIdx.x * 64;
    if (base > TOT - 64) base = TOT - 64;   // tail overlap: identical stores

    if (t < 64) {
        int e = base + t;
        int s, d;
        if (e < EE) { s = clampN(ei[e]); d = clampN(ei[EE + e]); }
        else { s = e - EE; d = e - EE; }
        s_src[t] = s; s_dst[t] = d;
    }
    // stage edge attrs: 4 threads per edge, 16 floats each
    {
        int el = t >> 2, part = t & 3;
        int e = base + el;
        const float* p = (e < EE) ? (eattr + (size_t)e * 64) : (g_loop_attr + (size_t)(e - EE) * 64);
        float* q = &EA_s[el * EAS + part * 16];
#pragma unroll
        for (int r = 0; r < 4; r++)
            *(float4*)(q + r * 4) = *(const float4*)&p[part * 16 + r * 4];
    }
    __syncthreads();

    int grp = lane >> 2;     // 0..7
    int thr = lane & 3;      // 0..3
    int row0 = mt * 16 + grp;

#pragma unroll
    for (int quarter = 0; quarter < 4; quarter++) {
        float acc[4][4];
#pragma unroll
        for (int nt = 0; nt < 4; nt++)
#pragma unroll
            for (int q = 0; q < 4; q++) acc[nt][q] = 0.f;

        for (int kc = 0; kc < 8; kc++) {
            __syncthreads();
            // stage B k-chunk: 8 k-rows x 64 cols (hi & lo), 2 elems/thread each
#pragma unroll
            for (int r = 0; r < 2; r++) {
                int i = t + r * 256;
                int kk = i >> 6, c = i & 63;
                int gidx = (kc * 8 + kk) * 256 + quarter * 64 + c;
                B_hi[kk * BS + c] = g_WeT_hi[gidx];
                B_lo[kk * BS + c] = g_WeT_lo[gidx];
            }
            __syncthreads();

            float a0 = EA_s[row0 * EAS + kc * 8 + thr];
            float a1 = EA_s[(row0 + 8) * EAS + kc * 8 + thr];
            float a2 = EA_s[row0 * EAS + kc * 8 + thr + 4];
            float a3 = EA_s[(row0 + 8) * EAS + kc * 8 + thr + 4];
            uint32_t ah0 = f2tf32(a0), ah1 = f2tf32(a1), ah2 = f2tf32(a2), ah3 = f2tf32(a3);
            uint32_t al0 = f2tf32(a0 - __uint_as_float(ah0));
            uint32_t al1 = f2tf32(a1 - __uint_as_float(ah1));
            uint32_t al2 = f2tf32(a2 - __uint_as_float(ah2));
            uint32_t al3 = f2tf32(a3 - __uint_as_float(ah3));

#pragma unroll
            for (int nt = 0; nt < 4; nt++) {
                int ccol = ng * 32 + nt * 8 + grp;
                uint32_t bh0 = __float_as_uint(B_hi[thr * BS + ccol]);
                uint32_t bh1 = __float_as_uint(B_hi[(thr + 4) * BS + ccol]);
                uint32_t bl0 = __float_as_uint(B_lo[thr * BS + ccol]);
                uint32_t bl1 = __float_as_uint(B_lo[(thr + 4) * BS + ccol]);
                asm("mma.sync.aligned.m16n8k8.row.col.f32.tf32.tf32.f32 "
                    "{%0,%1,%2,%3}, {%4,%5,%6,%7}, {%8,%9}, {%0,%1,%2,%3};"
                    : "+f"(acc[nt][0]), "+f"(acc[nt][1]), "+f"(acc[nt][2]), "+f"(acc[nt][3])
                    : "r"(al0), "r"(al1), "r"(al2), "r"(al3), "r"(bh0), "r"(bh1));
                asm("mma.sync.aligned.m16n8k8.row.col.f32.tf32.tf32.f32 "
                    "{%0,%1,%2,%3}, {%4,%5,%6,%7}, {%8,%9}, {%0,%1,%2,%3};"
                    : "+f"(acc[nt][0]), "+f"(acc[nt][1]), "+f"(acc[nt][2]), "+f"(acc[nt][3])
                    : "r"(ah0), "r"(ah1), "r"(ah2), "r"(ah3), "r"(bl0), "r"(bl1));
                asm("mma.sync.aligned.m16n8k8.row.col.f32.tf32.tf32.f32 "
                    "{%0,%1,%2,%3}, {%4,%5,%6,%7}, {%8,%9}, {%0,%1,%2,%3};"
                    : "+f"(acc[nt][0]), "+f"(acc[nt][1]), "+f"(acc[nt][2]), "+f"(acc[nt][3])
                    : "r"(ah0), "r"(ah1), "r"(ah2), "r"(ah3), "r"(bh0), "r"(bh1));
            }
        }

        __syncthreads();
#pragma unroll
        for (int nt = 0; nt < 4; nt++) {
            int cb = ng * 32 + nt * 8 + 2 * thr;
            EP_s[row0 * EPS + cb]           = acc[nt][0];
            EP_s[row0 * EPS + cb + 1]       = acc[nt][1];
            EP_s[(row0 + 8) * EPS + cb]     = acc[nt][2];
            EP_s[(row0 + 8) * EPS + cb + 1] = acc[nt][3];
        }
        __syncthreads();

        // epilogue: 4 threads per edge, 16 cols each; quarter == head
        {
            int el = t >> 2, sub = t & 3;
            int c0 = sub * 16;
            int src = s_src[el], dst = s_dst[el];
            const float* xlp = g_xl + (size_t)src * 256 + quarter * 64 + c0;
            const float* xrp = g_xr + (size_t)dst * 256 + quarter * 64 + c0;
            const float* epp = &EP_s[el * EPS + c0];
            const float* ats = &att_s[quarter * 64 + c0];
            float s = 0.f;
#pragma unroll
            for (int q4 = 0; q4 < 4; q4++) {
                float4 ev = *(const float4*)&epp[q4 * 4];
                float4 lv = *(const float4*)&xlp[q4 * 4];
                float4 rv = *(const float4*)&xrp[q4 * 4];
                float4 av = *(const float4*)&ats[q4 * 4];
                float m0 = ev.x + lv.x + rv.x; m0 = (m0 >= 0.f) ? m0 : 0.2f * m0;
                float m1 = ev.y + lv.y + rv.y; m1 = (m1 >= 0.f) ? m1 : 0.2f * m1;
                float m2 = ev.z + lv.z + rv.z; m2 = (m2 >= 0.f) ? m2 : 0.2f * m2;
                float m3 = ev.w + lv.w + rv.w; m3 = (m3 >= 0.f) ? m3 : 0.2f * m3;
                s = fmaf(m0, av.x, s); s = fmaf(m1, av.y, s);
                s = fmaf(m2, av.z, s); s = fmaf(m3, av.w, s);
            }
            s += __shfl_xor_sync(FULLMASK, s, 1);
            s += __shfl_xor_sync(FULLMASK, s, 2);
            if (sub == 0)
                g_logits[(size_t)(base + el) * 4 + quarter] = s;
        }
        __syncthreads();
    }
}

// ---------------- per-node softmax + aggregation + SiLU + LayerNorm ----------------
__global__ void k_node(const int* __restrict__ ei, const float* __restrict__ bias,
                       const float* __restrict__ gamma, const float* __restrict__ beta,
                       float* __restrict__ out_h) {
    __shared__ float red[256];
    __shared__ float s_mx[4];
    __shared__ float s_inv[4];
    __shared__ float s_alpha[64 * 4];
    __shared__ int   s_srcs[64];
    __shared__ float s_mu, s_var;
    int n = blockIdx.x, t = threadIdx.x;
    int start = g_rowptr[n];
    int deg = g_rowptr[n + 1] - start;
    int cnt = deg + 1;
    int h4 = t & 3;

    float lm = -1e30f;
    for (int i = t >> 2; i < cnt; i += 64) {
        int e = (i < deg) ? g_eids[start + i] : (EE + n);
        lm = fmaxf(lm, g_logits[(size_t)e * 4 + h4]);
    }
    red[t] = lm;
    __syncthreads();
    if (t < 4) {
        float m = -1e30f;
        for (int j = t; j < 256; j += 4) m = fmaxf(m, red[j]);
        s_mx[t] = m;
    }
    __syncthreads();
    float mxh = s_mx[h4];
    float ls = 0.f;
    for (int i = t >> 2; i < cnt; i += 64) {
        int e = (i < deg) ? g_eids[start + i] : (EE + n);
        ls += __expf(g_logits[(size_t)e * 4 + h4] - mxh);
    }
    red[t] = ls;
    __syncthreads();
    if (t < 4) {
        float sum = 0.f;
        for (int j = t; j < 256; j += 4) sum += red[j];
        g_den[n * 4 + t] = sum;
        g_mx[n * 4 + t] = s_mx[t];
        s_inv[t] = 1.0f / sum;
    }
    __syncthreads();

    int c = t, hh = c >> 6;
    float acc = 0.f;
    for (int bb = 0; bb < cnt; bb += 64) {
        int m = min(64, cnt - bb);
        __syncthreads();
        if (t < m) {
            int i = bb + t;
            int e = (i < deg) ? g_eids[start + i] : (EE + n);
            s_srcs[t] = (e < EE) ? clampN(ei[e]) : n;
            float4 lg = *(const float4*)&g_logits[(size_t)e * 4];
            s_alpha[t * 4 + 0] = __expf(lg.x - s_mx[0]) * s_inv[0];
            s_alpha[t * 4 + 1] = __expf(lg.y - s_mx[1]) * s_inv[1];
            s_alpha[t * 4 + 2] = __expf(lg.z - s_mx[2]) * s_inv[2];
            s_alpha[t * 4 + 3] = __expf(lg.w - s_mx[3]) * s_inv[3];
        }
        __syncthreads();
        for (int i = 0; i < m; i++)
            acc = fmaf(s_alpha[i * 4 + hh], g_xl[(size_t)s_srcs[i] * 256 + c], acc);
    }

    float v = acc + bias[c];
    v = v / (1.0f + __expf(-v));   // SiLU
    __syncthreads();
    red[t] = v;
    __syncthreads();
    for (int s = 128; s > 0; s >>= 1) { if (t < s) red[t] += red[t + s]; __syncthreads(); }
    if (t == 0) s_mu = red[0] * (1.0f / 256.0f);
    __syncthreads();
    float d = v - s_mu;
    red[t] = d * d;
    __syncthreads();
    for (int s = 128; s > 0; s >>= 1) { if (t < s) red[t] += red[t + s]; __syncthreads(); }
    if (t == 0) s_var = red[0] * (1.0f / 256.0f);
    __syncthreads();
    out_h[(size_t)n * 256 + c] = d * rsqrtf(s_var + 1e-5f) * gamma[c] + beta[c];
}

// ---------------- alpha writeback ----------------
__global__ void k_alpha(const int* __restrict__ ei, float* __restrict__ out_alpha) {
    long long id = (long long)blockIdx.x * blockDim.x + threadIdx.x;
    if (id >= (long long)TOT * 4) return;
    long long e = id >> 2;
    int h = (int)(id & 3);
    int dn = (e < EE) ? clampN(ei[EE + e]) : (int)(e - EE);
    out_alpha[id] = __expf(g_logits[id] - g_mx[dn * 4 + h]) / g_den[dn * 4 + h];
}

// ---------------- launch (kernel launches ONLY — graph-capturable) ----------------
extern "C" void kernel_launch(void* const* d_in, const int* in_sizes, int n_in,
                              void* d_out, int out_size) {
    const float* x     = (const float*)d_in[0];
    const int*   ei    = (const int*)d_in[1];     // int32 (JAX x64-disabled)
    const float* eattr = (const float*)d_in[2];
    const float* Wl    = (const float*)d_in[3];
    const float* bl    = (const float*)d_in[4];
    const float* Wr    = (const float*)d_in[5];
    const float* br    = (const float*)d_in[6];
    const float* We    = (const float*)d_in[7];
    const float* att   = (const float*)d_in[8];
    const float* bias  = (const float*)d_in[9];
    const float* gamma = (const float*)d_in[10];
    const float* beta  = (const float*)d_in[11];

    float* out_h = (float*)d_out;
    float* out_alpha = out_h + (size_t)NN * HCv;

    k_init<<<(NN + 255) / 256, 256>>>();
    k_count<<<(EE + 255) / 256, 256>>>(ei);
    k_scan<<<1, 1024>>>();
    k_fill<<<(EE + 255) / 256, 256>>>(ei);

    k_prep_we<<<(EDv * HCv + 255) / 256, 256>>>(We);

    dim3 pg((NN + 63) / 64, 4);
    k_proj2<<<pg, 256>>>(x, Wl, bl, Wr, br);

    k_loopattr<<<(NN + 7) / 8, 256>>>(eattr);

    k_logits_mma<<<(TOT + 63) / 64, 256>>>(ei, eattr, att);

    k_node<<<NN, 256>>>(ei, bias, gamma, beta, out_h);

    long long na = (long long)TOT * 4;
    k_alpha<<<(int)((na + 255) / 256), 256>>>(ei, out_alpha);
}

// round 6
// speedup vs baseline: 1.4855x; 1.0410x over previous
#include <cuda_runtime.h>
#include <cstdint>

#define NN 10000
#define EE 320000
#define HCv 256
#define EDv 64
#define TOT (EE + NN)
#define FULLMASK 0xffffffffu

static __device__ __forceinline__ int clampN(int v) {
    v = v < 0 ? 0 : v;
    return v > (NN - 1) ? (NN - 1) : v;
}

static __device__ __forceinline__ uint32_t f2tf32(float x) {
    uint32_t r;
    asm("cvt.rna.tf32.f32 %0, %1;" : "=r"(r) : "f"(x));
    return r;
}

// ---------------- scratch (device globals; no allocations allowed) ----------------
static __device__ float g_xl[NN * HCv];
static __device__ float g_xr[NN * HCv];
static __device__ float g_logits[TOT * 4];
static __device__ float g_loop_attr[NN * EDv];
static __device__ float g_WeT_hi[EDv * HCv];      // k-major [64][256]
static __device__ float g_WeT_lo[EDv * HCv];
static __device__ float g_mx[NN * 4];
static __device__ float g_den[NN * 4];
static __device__ int   g_deg[NN];
static __device__ int   g_rowptr[NN + 1];
static __device__ int   g_cursor[NN];
static __device__ int   g_eids[EE];

// ---------------- CSR init + We tf32 split (merged) ----------------
__global__ void k_init_prep(const float* __restrict__ We) {
    int i = blockIdx.x * blockDim.x + threadIdx.x;
    if (i < NN) { g_deg[i] = 0; g_cursor[i] = 0; }
    if (i < EDv * HCv) {
        int c = i >> 6, k = i & 63;
        float v = We[i];
        uint32_t hb = f2tf32(v);
        float hf = __uint_as_float(hb);
        uint32_t lb = f2tf32(v - hf);
        g_WeT_hi[k * 256 + c] = hf;
        g_WeT_lo[k * 256 + c] = __uint_as_float(lb);
    }
}

__global__ void k_count(const int* __restrict__ ei) {
    int e = blockIdx.x * blockDim.x + threadIdx.x;
    if (e < EE) atomicAdd(&g_deg[clampN(ei[EE + e])], 1);
}

__global__ void k_scan() {
    __shared__ int s[1024];
    __shared__ int carry_s;
    int t = threadIdx.x;
    if (t == 0) carry_s = 0;
    __syncthreads();
    for (int base = 0; base < NN; base += 1024) {
        int v = (base + t < NN) ? g_deg[base + t] : 0;
        s[t] = v;
        __syncthreads();
        for (int off = 1; off < 1024; off <<= 1) {
            int y = (t >= off) ? s[t - off] : 0;
            __syncthreads();
            s[t] += y;
            __syncthreads();
        }
        int carry = carry_s;
        if (base + t < NN) g_rowptr[base + t] = carry + s[t] - v;
        __syncthreads();
        if (t == 0) carry_s = carry + s[1023];
        __syncthreads();
    }
    if (t == 0) g_rowptr[NN] = carry_s;
}

__global__ void k_fill(const int* __restrict__ ei) {
    int e = blockIdx.x * blockDim.x + threadIdx.x;
    if (e < EE) {
        int d = clampN(ei[EE + e]);
        int pos = g_rowptr[d] + atomicAdd(&g_cursor[d], 1);
        if (pos >= 0 && pos < EE) g_eids[pos] = e;
    }
}

// ---------------- fused node projections: xl and xr in one pass over X ----------------
__global__ void k_proj2(const float* __restrict__ X, const float* __restrict__ Wl,
                        const float* __restrict__ bl, const float* __restrict__ Wr,
                        const float* __restrict__ br) {
    __shared__ float As[16][68];
    __shared__ float Wls[16][68];
    __shared__ float Wrs[16][68];
    int t  = threadIdx.x;
    int tx = t & 15, ty = t >> 4;
    int bm = blockIdx.x * 64, bj = blockIdx.y * 64;
    int lrow = t >> 2, lk = (t & 3) * 4;
    float accl[4][4] = {{0.f,0.f,0.f,0.f},{0.f,0.f,0.f,0.f},{0.f,0.f,0.f,0.f},{0.f,0.f,0.f,0.f}};
    float accr[4][4] = {{0.f,0.f,0.f,0.f},{0.f,0.f,0.f,0.f},{0.f,0.f,0.f,0.f},{0.f,0.f,0.f,0.f}};
    for (int k0 = 0; k0 < 256; k0 += 16) {
        float4 av = make_float4(0.f, 0.f, 0.f, 0.f);
        int arow = bm + lrow;
        if (arow < NN) av = *(const float4*)&X[(size_t)arow * 256 + k0 + lk];
        As[lk + 0][lrow] = av.x; As[lk + 1][lrow] = av.y;
        As[lk + 2][lrow] = av.z; As[lk + 3][lrow] = av.w;
        float4 wv = *(const float4*)&Wl[(size_t)(bj + lrow) * 256 + k0 + lk];
        Wls[lk + 0][lrow] = wv.x; Wls[lk + 1][lrow] = wv.y;
        Wls[lk + 2][lrow] = wv.z; Wls[lk + 3][lrow] = wv.w;
        float4 uv = *(const float4*)&Wr[(size_t)(bj + lrow) * 256 + k0 + lk];
        Wrs[lk + 0][lrow] = uv.x; Wrs[lk + 1][lrow] = uv.y;
        Wrs[lk + 2][lrow] = uv.z; Wrs[lk + 3][lrow] = uv.w;
        __syncthreads();
#pragma unroll
        for (int kk = 0; kk < 16; kk++) {
            float4 a4 = *(const float4*)&As[kk][ty * 4];
            float4 w4 = *(const float4*)&Wls[kk][tx * 4];
            float4 u4 = *(const float4*)&Wrs[kk][tx * 4];
            accl[0][0] += a4.x * w4.x; accl[0][1] += a4.x * w4.y; accl[0][2] += a4.x * w4.z; accl[0][3] += a4.x * w4.w;
            accl[1][0] += a4.y * w4.x; accl[1][1] += a4.y * w4.y; accl[1][2] += a4.y * w4.z; accl[1][3] += a4.y * w4.w;
            accl[2][0] += a4.z * w4.x; accl[2][1] += a4.z * w4.y; accl[2][2] += a4.z * w4.z; accl[2][3] += a4.z * w4.w;
            accl[3][0] += a4.w * w4.x; accl[3][1] += a4.w * w4.y; accl[3][2] += a4.w * w4.z; accl[3][3] += a4.w * w4.w;
            accr[0][0] += a4.x * u4.x; accr[0][1] += a4.x * u4.y; accr[0][2] += a4.x * u4.z; accr[0][3] += a4.x * u4.w;
            accr[1][0] += a4.y * u4.x; accr[1][1] += a4.y * u4.y; accr[1][2] += a4.y * u4.z; accr[1][3] += a4.y * u4.w;
            accr[2][0] += a4.z * u4.x; accr[2][1] += a4.z * u4.y; accr[2][2] += a4.z * u4.z; accr[2][3] += a4.z * u4.w;
            accr[3][0] += a4.w * u4.x; accr[3][1] += a4.w * u4.y; accr[3][2] += a4.w * u4.z; accr[3][3] += a4.w * u4.w;
        }
        __syncthreads();
    }
#pragma unroll
    for (int i = 0; i < 4; i++) {
        int row = bm + ty * 4 + i;
        if (row < NN) {
#pragma unroll
            for (int j = 0; j < 4; j++) {
                int col = bj + tx * 4 + j;
                g_xl[(size_t)row * 256 + col] = accl[i][j] + bl[col];
                g_xr[(size_t)row * 256 + col] = accr[i][j] + br[col];
            }
        }
    }
}

// ---------------- self-loop attr = mean of incoming edge_attr ----------------
__global__ void k_loopattr(const float* __restrict__ ea) {
    int w = blockIdx.x * (blockDim.x >> 5) + (threadIdx.x >> 5);
    int lane = threadIdx.x & 31;
    if (w >= NN) return;
    int start = g_rowptr[w];
    int deg = g_rowptr[w + 1] - start;
    float a0 = 0.f, a1 = 0.f;
    for (int i = 0; i < deg; i++) {
        int e = g_eids[start + i];
        a0 += ea[(size_t)e * 64 + lane];
        a1 += ea[(size_t)e * 64 + 32 + lane];
    }
    float inv = 1.0f / (float)max(deg, 1);
    g_loop_attr[w * 64 + lane] = a0 * inv;
    g_loop_attr[w * 64 + 32 + lane] = a1 * inv;
}

// ---------------- edge logits via split-tf32 mma, 64 edges/block, kc-outer ----------------
// 8 warps = 4 M-tiles (16 edges) x 2 N-groups (32 cols per 64-col quarter).
// B staged per kc (8 k-rows x 256 cols hi+lo); A converted once per kc;
// quarter x nt fully unrolled -> 48 back-to-back MMAs per thread per kc.
#define EAS 72    // EA_s row stride
#define BSQ 264   // B row stride (full 256 cols + pad)
#define EPS 68    // EP row stride

__global__ __launch_bounds__(256) void k_logits_mma(const int* __restrict__ ei,
                                                    const float* __restrict__ eattr,
                                                    const float* __restrict__ att) {
    __shared__ float EA_s[64 * EAS];       // 18.4 KB
    __shared__ float B_hi[8 * BSQ];        // 8.45 KB
    __shared__ float B_lo[8 * BSQ];        // 8.45 KB
    __shared__ float EP_s[64 * EPS];       // 17.4 KB (one quarter at a time)
    __shared__ float att_s[256];
    __shared__ int   s_src[64], s_dst[64];

    int t = threadIdx.x;
    int lane = t & 31;
    int warp = t >> 5;
    int mt = warp >> 1;          // M-tile 0..3 (16 edges each)
    int ng = warp & 1;           // N-group 0..1 (32 cols of each quarter)

    att_s[t] = att[t];

    int base = blockIdx.x * 64;
    if (base > TOT - 64) base = TOT - 64;   // tail overlap: identical stores

    if (t < 64) {
        int e = base + t;
        int s, d;
        if (e < EE) { s = clampN(ei[e]); d = clampN(ei[EE + e]); }
        else { s = e - EE; d = e - EE; }
        s_src[t] = s; s_dst[t] = d;
    }
    // stage edge attrs: 4 threads per edge, 16 floats each
    {
        int el = t >> 2, part = t & 3;
        int e = base + el;
        const float* p = (e < EE) ? (eattr + (size_t)e * 64) : (g_loop_attr + (size_t)(e - EE) * 64);
        float* q = &EA_s[el * EAS + part * 16];
#pragma unroll
        for (int r = 0; r < 4; r++)
            *(float4*)(q + r * 4) = *(const float4*)&p[part * 16 + r * 4];
    }

    int grp = lane >> 2;     // 0..7
    int thr = lane & 3;      // 0..3
    int row0 = mt * 16 + grp;

    float acc[4][4][4];      // [quarter][nt][frag]
#pragma unroll
    for (int qq = 0; qq < 4; qq++)
#pragma unroll
        for (int nt = 0; nt < 4; nt++)
#pragma unroll
            for (int q = 0; q < 4; q++) acc[qq][nt][q] = 0.f;

    __syncthreads();

    for (int kc = 0; kc < 8; kc++) {
        if (kc) __syncthreads();   // protect B overwrite
        // stage B k-chunk: 8 k-rows x 256 cols (hi & lo)
#pragma unroll
        for (int r = 0; r < 8; r++) {
            int i = t + r * 256;
            int kk = i >> 8, c = i & 255;
            int gidx = (kc * 8 + kk) * 256 + c;
            B_hi[kk * BSQ + c] = g_WeT_hi[gidx];
            B_lo[kk * BSQ + c] = g_WeT_lo[gidx];
        }
        __syncthreads();

        // A fragment for this warp's 16-edge tile (converted once per kc)
        float a0 = EA_s[row0 * EAS + kc * 8 + thr];
        float a1 = EA_s[(row0 + 8) * EAS + kc * 8 + thr];
        float a2 = EA_s[row0 * EAS + kc * 8 + thr + 4];
        float a3 = EA_s[(row0 + 8) * EAS + kc * 8 + thr + 4];
        uint32_t ah0 = f2tf32(a0), ah1 = f2tf32(a1), ah2 = f2tf32(a2), ah3 = f2tf32(a3);
        uint32_t al0 = f2tf32(a0 - __uint_as_float(ah0));
        uint32_t al1 = f2tf32(a1 - __uint_as_float(ah1));
        uint32_t al2 = f2tf32(a2 - __uint_as_float(ah2));
        uint32_t al3 = f2tf32(a3 - __uint_as_float(ah3));

#pragma unroll
        for (int qq = 0; qq < 4; qq++) {
#pragma unroll
            for (int nt = 0; nt < 4; nt++) {
                int ccol = qq * 64 + ng * 32 + nt * 8 + grp;
                uint32_t bh0 = __float_as_uint(B_hi[thr * BSQ + ccol]);
                uint32_t bh1 = __float_as_uint(B_hi[(thr + 4) * BSQ + ccol]);
                uint32_t bl0 = __float_as_uint(B_lo[thr * BSQ + ccol]);
                uint32_t bl1 = __float_as_uint(B_lo[(thr + 4) * BSQ + ccol]);
                asm("mma.sync.aligned.m16n8k8.row.col.f32.tf32.tf32.f32 "
                    "{%0,%1,%2,%3}, {%4,%5,%6,%7}, {%8,%9}, {%0,%1,%2,%3};"
                    : "+f"(acc[qq][nt][0]), "+f"(acc[qq][nt][1]), "+f"(acc[qq][nt][2]), "+f"(acc[qq][nt][3])
                    : "r"(al0), "r"(al1), "r"(al2), "r"(al3), "r"(bh0), "r"(bh1));
                asm("mma.sync.aligned.m16n8k8.row.col.f32.tf32.tf32.f32 "
                    "{%0,%1,%2,%3}, {%4,%5,%6,%7}, {%8,%9}, {%0,%1,%2,%3};"
                    : "+f"(acc[qq][nt][0]), "+f"(acc[qq][nt][1]), "+f"(acc[qq][nt][2]), "+f"(acc[qq][nt][3])
                    : "r"(ah0), "r"(ah1), "r"(ah2), "r"(ah3), "r"(bl0), "r"(bl1));
                asm("mma.sync.aligned.m16n8k8.row.col.f32.tf32.tf32.f32 "
                    "{%0,%1,%2,%3}, {%4,%5,%6,%7}, {%8,%9}, {%0,%1,%2,%3};"
                    : "+f"(acc[qq][nt][0]), "+f"(acc[qq][nt][1]), "+f"(acc[qq][nt][2]), "+f"(acc[qq][nt][3])
                    : "r"(ah0), "r"(ah1), "r"(ah2), "r"(ah3), "r"(bh0), "r"(bh1));
            }
        }
    }

    // epilogue per quarter: dump EP fragments, gather xl/xr, leaky+att-dot, reduce
#pragma unroll
    for (int quarter = 0; quarter < 4; quarter++) {
        __syncthreads();
#pragma unroll
        for (int nt = 0; nt < 4; nt++) {
            int cb = ng * 32 + nt * 8 + 2 * thr;
            EP_s[row0 * EPS + cb]           = acc[quarter][nt][0];
            EP_s[row0 * EPS + cb + 1]       = acc[quarter][nt][1];
            EP_s[(row0 + 8) * EPS + cb]     = acc[quarter][nt][2];
            EP_s[(row0 + 8) * EPS + cb + 1] = acc[quarter][nt][3];
        }
        __syncthreads();
        {
            int el = t >> 2, sub = t & 3;
            int c0 = sub * 16;
            int src = s_src[el], dst = s_dst[el];
            const float* xlp = g_xl + (size_t)src * 256 + quarter * 64 + c0;
            const float* xrp = g_xr + (size_t)dst * 256 + quarter * 64 + c0;
            const float* epp = &EP_s[el * EPS + c0];
            const float* ats = &att_s[quarter * 64 + c0];
            float s = 0.f;
#pragma unroll
            for (int q4 = 0; q4 < 4; q4++) {
                float4 ev = *(const float4*)&epp[q4 * 4];
                float4 lv = *(const float4*)&xlp[q4 * 4];
                float4 rv = *(const float4*)&xrp[q4 * 4];
                float4 av = *(const float4*)&ats[q4 * 4];
                float m0 = ev.x + lv.x + rv.x; m0 = (m0 >= 0.f) ? m0 : 0.2f * m0;
                float m1 = ev.y + lv.y + rv.y; m1 = (m1 >= 0.f) ? m1 : 0.2f * m1;
                float m2 = ev.z + lv.z + rv.z; m2 = (m2 >= 0.f) ? m2 : 0.2f * m2;
                float m3 = ev.w + lv.w + rv.w; m3 = (m3 >= 0.f) ? m3 : 0.2f * m3;
                s = fmaf(m0, av.x, s); s = fmaf(m1, av.y, s);
                s = fmaf(m2, av.z, s); s = fmaf(m3, av.w, s);
            }
            s += __shfl_xor_sync(FULLMASK, s, 1);
            s += __shfl_xor_sync(FULLMASK, s, 2);
            if (sub == 0)
                g_logits[(size_t)(base + el) * 4 + quarter] = s;
        }
    }
}

// ---------------- per-node softmax + aggregation + SiLU + LayerNorm ----------------
__global__ void k_node(const int* __restrict__ ei, const float* __restrict__ bias,
                       const float* __restrict__ gamma, const float* __restrict__ beta,
                       float* __restrict__ out_h) {
    __shared__ float red[256];
    __shared__ float s_mx[4];
    __shared__ float s_inv[4];
    __shared__ float s_alpha[64 * 4];
    __shared__ int   s_srcs[64];
    __shared__ float s_mu, s_var;
    int n = blockIdx.x, t = threadIdx.x;
    int start = g_rowptr[n];
    int deg = g_rowptr[n + 1] - start;
    int cnt = deg + 1;
    int h4 = t & 3;

    float lm = -1e30f;
    for (int i = t >> 2; i < cnt; i += 64) {
        int e = (i < deg) ? g_eids[start + i] : (EE + n);
        lm = fmaxf(lm, g_logits[(size_t)e * 4 + h4]);
    }
    red[t] = lm;
    __syncthreads();
    if (t < 4) {
        float m = -1e30f;
        for (int j = t; j < 256; j += 4) m = fmaxf(m, red[j]);
        s_mx[t] = m;
    }
    __syncthreads();
    float mxh = s_mx[h4];
    float ls = 0.f;
    for (int i = t >> 2; i < cnt; i += 64) {
        int e = (i < deg) ? g_eids[start + i] : (EE + n);
        ls += __expf(g_logits[(size_t)e * 4 + h4] - mxh);
    }
    red[t] = ls;
    __syncthreads();
    if (t < 4) {
        float sum = 0.f;
        for (int j = t; j < 256; j += 4) sum += red[j];
        g_den[n * 4 + t] = sum;
        g_mx[n * 4 + t] = s_mx[t];
        s_inv[t] = 1.0f / sum;
    }
    __syncthreads();

    int c = t, hh = c >> 6;
    float acc = 0.f;
    for (int bb = 0; bb < cnt; bb += 64) {
        int m = min(64, cnt - bb);
        __syncthreads();
        if (t < m) {
            int i = bb + t;
            int e = (i < deg) ? g_eids[start + i] : (EE + n);
            s_srcs[t] = (e < EE) ? clampN(ei[e]) : n;
            float4 lg = *(const float4*)&g_logits[(size_t)e * 4];
            s_alpha[t * 4 + 0] = __expf(lg.x - s_mx[0]) * s_inv[0];
            s_alpha[t * 4 + 1] = __expf(lg.y - s_mx[1]) * s_inv[1];
            s_alpha[t * 4 + 2] = __expf(lg.z - s_mx[2]) * s_inv[2];
            s_alpha[t * 4 + 3] = __expf(lg.w - s_mx[3]) * s_inv[3];
        }
        __syncthreads();
        for (int i = 0; i < m; i++)
            acc = fmaf(s_alpha[i * 4 + hh], g_xl[(size_t)s_srcs[i] * 256 + c], acc);
    }

    float v = acc + bias[c];
    v = v / (1.0f + __expf(-v));   // SiLU
    __syncthreads();
    red[t] = v;
    __syncthreads();
    for (int s = 128; s > 0; s >>= 1) { if (t < s) red[t] += red[t + s]; __syncthreads(); }
    if (t == 0) s_mu = red[0] * (1.0f / 256.0f);
    __syncthreads();
    float d = v - s_mu;
    red[t] = d * d;
    __syncthreads();
    for (int s = 128; s > 0; s >>= 1) { if (t < s) red[t] += red[t + s]; __syncthreads(); }
    if (t == 0) s_var = red[0] * (1.0f / 256.0f);
    __syncthreads();
    out_h[(size_t)n * 256 + c] = d * rsqrtf(s_var + 1e-5f) * gamma[c] + beta[c];
}

// ---------------- alpha writeback ----------------
__global__ void k_alpha(const int* __restrict__ ei, float* __restrict__ out_alpha) {
    long long id = (long long)blockIdx.x * blockDim.x + threadIdx.x;
    if (id >= (long long)TOT * 4) return;
    long long e = id >> 2;
    int h = (int)(id & 3);
    int dn = (e < EE) ? clampN(ei[EE + e]) : (int)(e - EE);
    out_alpha[id] = __expf(g_logits[id] - g_mx[dn * 4 + h]) / g_den[dn * 4 + h];
}

// ---------------- launch (kernel launches ONLY — graph-capturable) ----------------
extern "C" void kernel_launch(void* const* d_in, const int* in_sizes, int n_in,
                              void* d_out, int out_size) {
    const float* x     = (const float*)d_in[0];
    const int*   ei    = (const int*)d_in[1];     // int32 (JAX x64-disabled)
    const float* eattr = (const float*)d_in[2];
    const float* Wl    = (const float*)d_in[3];
    const float* bl    = (const float*)d_in[4];
    const float* Wr    = (const float*)d_in[5];
    const float* br    = (const float*)d_in[6];
    const float* We    = (const float*)d_in[7];
    const float* att   = (const float*)d_in[8];
    const float* bias  = (const float*)d_in[9];
    const float* gamma = (const float*)d_in[10];
    const float* beta  = (const float*)d_in[11];

    float* out_h = (float*)d_out;
    float* out_alpha = out_h + (size_t)NN * HCv;

    k_init_prep<<<(EDv * HCv + 255) / 256, 256>>>(We);   // covers NN too (16384 >= 10000)
    k_count<<<(EE + 255) / 256, 256>>>(ei);
    k_scan<<<1, 1024>>>();
    k_fill<<<(EE + 255) / 256, 256>>>(ei);

    dim3 pg((NN + 63) / 64, 4);
    k_proj2<<<pg, 256>>>(x, Wl, bl, Wr, br);

    k_loopattr<<<(NN + 7) / 8, 256>>>(eattr);

    k_logits_mma<<<(TOT + 63) / 64, 256>>>(ei, eattr, att);

    k_node<<<NN, 256>>>(ei, bias, gamma, beta, out_h);

    long long na = (long long)TOT * 4;
    k_alpha<<<(int)((na + 255) / 256), 256>>>(ei, out_alpha);
}

// round 7
// speedup vs baseline: 1.8099x; 1.2184x over previous
#include <cuda_runtime.h>
#include <cuda_fp16.h>
#include <cstdint>

#define NN 10000
#define EE 320000
#define HCv 256
#define EDv 64
#define TOT (EE + NN)
#define FULLMASK 0xffffffffu

static __device__ __forceinline__ int clampN(int v) {
    v = v < 0 ? 0 : v;
    return v > (NN - 1) ? (NN - 1) : v;
}

static __device__ __forceinline__ uint32_t pack_h2(float x, float y) {
    __half2 h = __floats2half2_rn(x, y);
    return *(uint32_t*)&h;
}

// ---------------- scratch (device globals; no allocations allowed) ----------------
static __device__ float    g_xl[NN * HCv];
static __device__ float    g_xr[NN * HCv];
static __device__ float    g_logits[TOT * 4];
static __device__ float    g_loop_attr[NN * EDv];
static __device__ uint32_t g_WeB_hi[32 * HCv];    // [k-pair][col] packed half2 (k, k+1)
static __device__ uint32_t g_WeB_lo[32 * HCv];    // residuals
static __device__ int      g_deg[NN];
static __device__ int      g_rowptr[NN + 1];
static __device__ int      g_cursor[NN];
static __device__ int      g_eids[EE];

// ---------------- CSR init + We fp16 hi/lo split (k-pair packed) ----------------
__global__ void k_init_prep(const float* __restrict__ We) {
    int i = blockIdx.x * blockDim.x + threadIdx.x;
    if (i < NN) { g_deg[i] = 0; g_cursor[i] = 0; }
    if (i < 32 * HCv) {
        int c = i & 255, k2 = i >> 8;
        float v0 = We[c * 64 + 2 * k2];
        float v1 = We[c * 64 + 2 * k2 + 1];
        __half h0 = __float2half_rn(v0), h1 = __float2half_rn(v1);
        float r0 = v0 - __half2float(h0);
        float r1 = v1 - __half2float(h1);
        g_WeB_hi[k2 * 256 + c] = pack_h2(__half2float(h0), __half2float(h1));
        g_WeB_lo[k2 * 256 + c] = pack_h2(r0, r1);
    }
}

__global__ void k_count(const int* __restrict__ ei) {
    int e = blockIdx.x * blockDim.x + threadIdx.x;
    if (e < EE) atomicAdd(&g_deg[clampN(ei[EE + e])], 1);
}

__global__ void k_scan() {
    __shared__ int s[1024];
    __shared__ int carry_s;
    int t = threadIdx.x;
    if (t == 0) carry_s = 0;
    __syncthreads();
    for (int base = 0; base < NN; base += 1024) {
        int v = (base + t < NN) ? g_deg[base + t] : 0;
        s[t] = v;
        __syncthreads();
        for (int off = 1; off < 1024; off <<= 1) {
            int y = (t >= off) ? s[t - off] : 0;
            __syncthreads();
            s[t] += y;
            __syncthreads();
        }
        int carry = carry_s;
        if (base + t < NN) g_rowptr[base + t] = carry + s[t] - v;
        __syncthreads();
        if (t == 0) carry_s = carry + s[1023];
        __syncthreads();
    }
    if (t == 0) g_rowptr[NN] = carry_s;
}

__global__ void k_fill(const int* __restrict__ ei) {
    int e = blockIdx.x * blockDim.x + threadIdx.x;
    if (e < EE) {
        int d = clampN(ei[EE + e]);
        int pos = g_rowptr[d] + atomicAdd(&g_cursor[d], 1);
        if (pos >= 0 && pos < EE) g_eids[pos] = e;
    }
}

// ---------------- fused node projections: xl and xr in one pass over X ----------------
__global__ void k_proj2(const float* __restrict__ X, const float* __restrict__ Wl,
                        const float* __restrict__ bl, const float* __restrict__ Wr,
                        const float* __restrict__ br) {
    __shared__ float As[16][68];
    __shared__ float Wls[16][68];
    __shared__ float Wrs[16][68];
    int t  = threadIdx.x;
    int tx = t & 15, ty = t >> 4;
    int bm = blockIdx.x * 64, bj = blockIdx.y * 64;
    int lrow = t >> 2, lk = (t & 3) * 4;
    float accl[4][4] = {{0.f,0.f,0.f,0.f},{0.f,0.f,0.f,0.f},{0.f,0.f,0.f,0.f},{0.f,0.f,0.f,0.f}};
    float accr[4][4] = {{0.f,0.f,0.f,0.f},{0.f,0.f,0.f,0.f},{0.f,0.f,0.f,0.f},{0.f,0.f,0.f,0.f}};
    for (int k0 = 0; k0 < 256; k0 += 16) {
        float4 av = make_float4(0.f, 0.f, 0.f, 0.f);
        int arow = bm + lrow;
        if (arow < NN) av = *(const float4*)&X[(size_t)arow * 256 + k0 + lk];
        As[lk + 0][lrow] = av.x; As[lk + 1][lrow] = av.y;
        As[lk + 2][lrow] = av.z; As[lk + 3][lrow] = av.w;
        float4 wv = *(const float4*)&Wl[(size_t)(bj + lrow) * 256 + k0 + lk];
        Wls[lk + 0][lrow] = wv.x; Wls[lk + 1][lrow] = wv.y;
        Wls[lk + 2][lrow] = wv.z; Wls[lk + 3][lrow] = wv.w;
        float4 uv = *(const float4*)&Wr[(size_t)(bj + lrow) * 256 + k0 + lk];
        Wrs[lk + 0][lrow] = uv.x; Wrs[lk + 1][lrow] = uv.y;
        Wrs[lk + 2][lrow] = uv.z; Wrs[lk + 3][lrow] = uv.w;
        __syncthreads();
#pragma unroll
        for (int kk = 0; kk < 16; kk++) {
            float4 a4 = *(const float4*)&As[kk][ty * 4];
            float4 w4 = *(const float4*)&Wls[kk][tx * 4];
            float4 u4 = *(const float4*)&Wrs[kk][tx * 4];
            accl[0][0] += a4.x * w4.x; accl[0][1] += a4.x * w4.y; accl[0][2] += a4.x * w4.z; accl[0][3] += a4.x * w4.w;
            accl[1][0] += a4.y * w4.x; accl[1][1] += a4.y * w4.y; accl[1][2] += a4.y * w4.z; accl[1][3] += a4.y * w4.w;
            accl[2][0] += a4.z * w4.x; accl[2][1] += a4.z * w4.y; accl[2][2] += a4.z * w4.z; accl[2][3] += a4.z * w4.w;
            accl[3][0] += a4.w * w4.x; accl[3][1] += a4.w * w4.y; accl[3][2] += a4.w * w4.z; accl[3][3] += a4.w * w4.w;
            accr[0][0] += a4.x * u4.x; accr[0][1] += a4.x * u4.y; accr[0][2] += a4.x * u4.z; accr[0][3] += a4.x * u4.w;
            accr[1][0] += a4.y * u4.x; accr[1][1] += a4.y * u4.y; accr[1][2] += a4.y * u4.z; accr[1][3] += a4.y * u4.w;
            accr[2][0] += a4.z * u4.x; accr[2][1] += a4.z * u4.y; accr[2][2] += a4.z * u4.z; accr[2][3] += a4.z * u4.w;
            accr[3][0] += a4.w * u4.x; accr[3][1] += a4.w * u4.y; accr[3][2] += a4.w * u4.z; accr[3][3] += a4.w * u4.w;
        }
        __syncthreads();
    }
#pragma unroll
    for (int i = 0; i < 4; i++) {
        int row = bm + ty * 4 + i;
        if (row < NN) {
#pragma unroll
            for (int j = 0; j < 4; j++) {
                int col = bj + tx * 4 + j;
                g_xl[(size_t)row * 256 + col] = accl[i][j] + bl[col];
                g_xr[(size_t)row * 256 + col] = accr[i][j] + br[col];
            }
        }
    }
}

// ---------------- self-loop attr = mean of incoming edge_attr ----------------
__global__ void k_loopattr(const float* __restrict__ ea) {
    int w = blockIdx.x * (blockDim.x >> 5) + (threadIdx.x >> 5);
    int lane = threadIdx.x & 31;
    if (w >= NN) return;
    int start = g_rowptr[w];
    int deg = g_rowptr[w + 1] - start;
    float a0 = 0.f, a1 = 0.f;
    for (int i = 0; i < deg; i++) {
        int e = g_eids[start + i];
        a0 += ea[(size_t)e * 64 + lane];
        a1 += ea[(size_t)e * 64 + 32 + lane];
    }
    float inv = 1.0f / (float)max(deg, 1);
    g_loop_attr[w * 64 + lane] = a0 * inv;
    g_loop_attr[w * 64 + 32 + lane] = a1 * inv;
}

// ---------------- edge logits via split-fp16 m16n8k16 mma, 64 edges/block ----------------
// 8 warps = 4 M-tiles (16 edges) x 2 N-groups. B packed half2 per k-pair.
// kc-outer (4 chunks of k16); C-fragment layout identical to the proven k8 path.
#define EAS 72    // EA_s row stride
#define BS2 264   // B row stride (uint32 half2 entries)
#define EPS 68    // EP row stride

__global__ __launch_bounds__(256) void k_logits_mma(const int* __restrict__ ei,
                                                    const float* __restrict__ eattr,
                                                    const float* __restrict__ att) {
    __shared__ float    EA_s[64 * EAS];      // 18.4 KB
    __shared__ uint32_t B_hi[8 * BS2];       // 8.45 KB (8 k-pairs x 256 cols)
    __shared__ uint32_t B_lo[8 * BS2];       // 8.45 KB
    __shared__ float    EP_s[64 * EPS];      // 17.4 KB
    __shared__ float    att_s[256];
    __shared__ int      s_src[64], s_dst[64];

    int t = threadIdx.x;
    int lane = t & 31;
    int warp = t >> 5;
    int mt = warp >> 1;          // M-tile 0..3
    int ng = warp & 1;           // N-group 0..1

    att_s[t] = att[t];

    int base = blockIdx.x * 64;
    if (base > TOT - 64) base = TOT - 64;   // tail overlap: identical stores

    if (t < 64) {
        int e = base + t;
        int s, d;
        if (e < EE) { s = clampN(ei[e]); d = clampN(ei[EE + e]); }
        else { s = e - EE; d = e - EE; }
        s_src[t] = s; s_dst[t] = d;
    }
    {
        int el = t >> 2, part = t & 3;
        int e = base + el;
        const float* p = (e < EE) ? (eattr + (size_t)e * 64) : (g_loop_attr + (size_t)(e - EE) * 64);
        float* q = &EA_s[el * EAS + part * 16];
#pragma unroll
        for (int r = 0; r < 4; r++)
            *(float4*)(q + r * 4) = *(const float4*)&p[part * 16 + r * 4];
    }

    int grp = lane >> 2;     // 0..7
    int thr = lane & 3;      // 0..3
    int row0 = mt * 16 + grp;

    float acc[4][4][4];      // [quarter][nt][frag]
#pragma unroll
    for (int qq = 0; qq < 4; qq++)
#pragma unroll
        for (int nt = 0; nt < 4; nt++)
#pragma unroll
            for (int q = 0; q < 4; q++) acc[qq][nt][q] = 0.f;

    __syncthreads();

    for (int kc = 0; kc < 4; kc++) {      // 4 chunks of K=16
        if (kc) __syncthreads();
        // stage B k-chunk: 8 k-pair rows x 256 cols (hi & lo)
#pragma unroll
        for (int r = 0; r < 8; r++) {
            int i = t + r * 256;
            int kk = i >> 8, c = i & 255;
            int gidx = (kc * 8 + kk) * 256 + c;
            B_hi[kk * BS2 + c] = g_WeB_hi[gidx];
            B_lo[kk * BS2 + c] = g_WeB_lo[gidx];
        }
        __syncthreads();

        // A fragments (m16n8k16): rows row0/row0+8, cols kc*16 + {thr*2,thr*2+1, +8,+9}
        int cA = kc * 16 + thr * 2;
        float x00 = EA_s[row0 * EAS + cA],         x01 = EA_s[row0 * EAS + cA + 1];
        float x10 = EA_s[(row0 + 8) * EAS + cA],   x11 = EA_s[(row0 + 8) * EAS + cA + 1];
        float x20 = EA_s[row0 * EAS + cA + 8],     x21 = EA_s[row0 * EAS + cA + 9];
        float x30 = EA_s[(row0 + 8) * EAS + cA + 8], x31 = EA_s[(row0 + 8) * EAS + cA + 9];

        __half h00 = __float2half_rn(x00), h01 = __float2half_rn(x01);
        __half h10 = __float2half_rn(x10), h11 = __float2half_rn(x11);
        __half h20 = __float2half_rn(x20), h21 = __float2half_rn(x21);
        __half h30 = __float2half_rn(x30), h31 = __float2half_rn(x31);
        uint32_t ah0 = pack_h2(__half2float(h00), __half2float(h01));
        uint32_t ah1 = pack_h2(__half2float(h10), __half2float(h11));
        uint32_t ah2 = pack_h2(__half2float(h20), __half2float(h21));
        uint32_t ah3 = pack_h2(__half2float(h30), __half2float(h31));
        uint32_t al0 = pack_h2(x00 - __half2float(h00), x01 - __half2float(h01));
        uint32_t al1 = pack_h2(x10 - __half2float(h10), x11 - __half2float(h11));
        uint32_t al2 = pack_h2(x20 - __half2float(h20), x21 - __half2float(h21));
        uint32_t al3 = pack_h2(x30 - __half2float(h30), x31 - __half2float(h31));

#pragma unroll
        for (int qq = 0; qq < 4; qq++) {
#pragma unroll
            for (int nt = 0; nt < 4; nt++) {
                int ccol = qq * 64 + ng * 32 + nt * 8 + grp;
                uint32_t bh0 = B_hi[thr * BS2 + ccol];
                uint32_t bh1 = B_hi[(thr + 4) * BS2 + ccol];
                uint32_t bl0 = B_lo[thr * BS2 + ccol];
                uint32_t bl1 = B_lo[(thr + 4) * BS2 + ccol];
                asm("mma.sync.aligned.m16n8k16.row.col.f32.f16.f16.f32 "
                    "{%0,%1,%2,%3}, {%4,%5,%6,%7}, {%8,%9}, {%0,%1,%2,%3};"
                    : "+f"(acc[qq][nt][0]), "+f"(acc[qq][nt][1]), "+f"(acc[qq][nt][2]), "+f"(acc[qq][nt][3])
                    : "r"(al0), "r"(al1), "r"(al2), "r"(al3), "r"(bh0), "r"(bh1));
                asm("mma.sync.aligned.m16n8k16.row.col.f32.f16.f16.f32 "
                    "{%0,%1,%2,%3}, {%4,%5,%6,%7}, {%8,%9}, {%0,%1,%2,%3};"
                    : "+f"(acc[qq][nt][0]), "+f"(acc[qq][nt][1]), "+f"(acc[qq][nt][2]), "+f"(acc[qq][nt][3])
                    : "r"(ah0), "r"(ah1), "r"(ah2), "r"(ah3), "r"(bl0), "r"(bl1));
                asm("mma.sync.aligned.m16n8k16.row.col.f32.f16.f16.f32 "
                    "{%0,%1,%2,%3}, {%4,%5,%6,%7}, {%8,%9}, {%0,%1,%2,%3};"
                    : "+f"(acc[qq][nt][0]), "+f"(acc[qq][nt][1]), "+f"(acc[qq][nt][2]), "+f"(acc[qq][nt][3])
                    : "r"(ah0), "r"(ah1), "r"(ah2), "r"(ah3), "r"(bh0), "r"(bh1));
            }
        }
    }

    // epilogue per quarter: dump EP fragments, gather xl/xr, leaky+att-dot, reduce
#pragma unroll
    for (int quarter = 0; quarter < 4; quarter++) {
        __syncthreads();
#pragma unroll
        for (int nt = 0; nt < 4; nt++) {
            int cb = ng * 32 + nt * 8 + 2 * thr;
            EP_s[row0 * EPS + cb]           = acc[quarter][nt][0];
            EP_s[row0 * EPS + cb + 1]       = acc[quarter][nt][1];
            EP_s[(row0 + 8) * EPS + cb]     = acc[quarter][nt][2];
            EP_s[(row0 + 8) * EPS + cb + 1] = acc[quarter][nt][3];
        }
        __syncthreads();
        {
            int el = t >> 2, sub = t & 3;
            int c0 = sub * 16;
            int src = s_src[el], dst = s_dst[el];
            const float* xlp = g_xl + (size_t)src * 256 + quarter * 64 + c0;
            const float* xrp = g_xr + (size_t)dst * 256 + quarter * 64 + c0;
            const float* epp = &EP_s[el * EPS + c0];
            const float* ats = &att_s[quarter * 64 + c0];
            float s = 0.f;
#pragma unroll
            for (int q4 = 0; q4 < 4; q4++) {
                float4 ev = *(const float4*)&epp[q4 * 4];
                float4 lv = *(const float4*)&xlp[q4 * 4];
                float4 rv = *(const float4*)&xrp[q4 * 4];
                float4 av = *(const float4*)&ats[q4 * 4];
                float m0 = ev.x + lv.x + rv.x; m0 = (m0 >= 0.f) ? m0 : 0.2f * m0;
                float m1 = ev.y + lv.y + rv.y; m1 = (m1 >= 0.f) ? m1 : 0.2f * m1;
                float m2 = ev.z + lv.z + rv.z; m2 = (m2 >= 0.f) ? m2 : 0.2f * m2;
                float m3 = ev.w + lv.w + rv.w; m3 = (m3 >= 0.f) ? m3 : 0.2f * m3;
                s = fmaf(m0, av.x, s); s = fmaf(m1, av.y, s);
                s = fmaf(m2, av.z, s); s = fmaf(m3, av.w, s);
            }
            s += __shfl_xor_sync(FULLMASK, s, 1);
            s += __shfl_xor_sync(FULLMASK, s, 2);
            if (sub == 0)
                g_logits[(size_t)(base + el) * 4 + quarter] = s;
        }
    }
}

// ---------------- per-node softmax + aggregation + SiLU + LayerNorm + alpha out ----------------
__global__ void k_node(const int* __restrict__ ei, const float* __restrict__ bias,
                       const float* __restrict__ gamma, const float* __restrict__ beta,
                       float* __restrict__ out_h, float* __restrict__ out_alpha) {
    __shared__ float red[256];
    __shared__ float s_mx[4];
    __shared__ float s_inv[4];
    __shared__ float s_alpha[64 * 4];
    __shared__ int   s_srcs[64];
    __shared__ float s_mu, s_var;
    int n = blockIdx.x, t = threadIdx.x;
    int start = g_rowptr[n];
    int deg = g_rowptr[n + 1] - start;
    int cnt = deg + 1;
    int h4 = t & 3;

    float lm = -1e30f;
    for (int i = t >> 2; i < cnt; i += 64) {
        int e = (i < deg) ? g_eids[start + i] : (EE + n);
        lm = fmaxf(lm, g_logits[(size_t)e * 4 + h4]);
    }
    red[t] = lm;
    __syncthreads();
    if (t < 4) {
        float m = -1e30f;
        for (int j = t; j < 256; j += 4) m = fmaxf(m, red[j]);
        s_mx[t] = m;
    }
    __syncthreads();
    float mxh = s_mx[h4];
    float ls = 0.f;
    for (int i = t >> 2; i < cnt; i += 64) {
        int e = (i < deg) ? g_eids[start + i] : (EE + n);
        ls += __expf(g_logits[(size_t)e * 4 + h4] - mxh);
    }
    red[t] = ls;
    __syncthreads();
    if (t < 4) {
        float sum = 0.f;
        for (int j = t; j < 256; j += 4) sum += red[j];
        s_inv[t] = 1.0f / sum;
    }
    __syncthreads();

    int c = t, hh = c >> 6;
    float acc = 0.f;
    for (int bb = 0; bb < cnt; bb += 64) {
        int m = min(64, cnt - bb);
        __syncthreads();
        if (t < m) {
            int i = bb + t;
            int e = (i < deg) ? g_eids[start + i] : (EE + n);
            s_srcs[t] = (e < EE) ? clampN(ei[e]) : n;
            float4 lg = *(const float4*)&g_logits[(size_t)e * 4];
            float a0 = __expf(lg.x - s_mx[0]) * s_inv[0];
            float a1 = __expf(lg.y - s_mx[1]) * s_inv[1];
            float a2 = __expf(lg.z - s_mx[2]) * s_inv[2];
            float a3 = __expf(lg.w - s_mx[3]) * s_inv[3];
            s_alpha[t * 4 + 0] = a0;
            s_alpha[t * 4 + 1] = a1;
            s_alpha[t * 4 + 2] = a2;
            s_alpha[t * 4 + 3] = a3;
            *(float4*)&out_alpha[(size_t)e * 4] = make_float4(a0, a1, a2, a3);
        }
        __syncthreads();
        for (int i = 0; i < m; i++)
            acc = fmaf(s_alpha[i * 4 + hh], g_xl[(size_t)s_srcs[i] * 256 + c], acc);
    }

    float v = acc + bias[c];
    v = v / (1.0f + __expf(-v));   // SiLU
    __syncthreads();
    red[t] = v;
    __syncthreads();
    for (int s = 128; s > 0; s >>= 1) { if (t < s) red[t] += red[t + s]; __syncthreads(); }
    if (t == 0) s_mu = red[0] * (1.0f / 256.0f);
    __syncthreads();
    float d = v - s_mu;
    red[t] = d * d;
    __syncthreads();
    for (int s = 128; s > 0; s >>= 1) { if (t < s) red[t] += red[t + s]; __syncthreads(); }
    if (t == 0) s_var = red[0] * (1.0f / 256.0f);
    __syncthreads();
    out_h[(size_t)n * 256 + c] = d * rsqrtf(s_var + 1e-5f) * gamma[c] + beta[c];
}

// ---------------- launch (kernel launches ONLY — graph-capturable) ----------------
extern "C" void kernel_launch(void* const* d_in, const int* in_sizes, int n_in,
                              void* d_out, int out_size) {
    const float* x     = (const float*)d_in[0];
    const int*   ei    = (const int*)d_in[1];     // int32 (JAX x64-disabled)
    const float* eattr = (const float*)d_in[2];
    const float* Wl    = (const float*)d_in[3];
    const float* bl    = (const float*)d_in[4];
    const float* Wr    = (const float*)d_in[5];
    const float* br    = (const float*)d_in[6];
    const float* We    = (const float*)d_in[7];
    const float* att   = (const float*)d_in[8];
    const float* bias  = (const float*)d_in[9];
    const float* gamma = (const float*)d_in[10];
    const float* beta  = (const float*)d_in[11];

    float* out_h = (float*)d_out;
    float* out_alpha = out_h + (size_t)NN * HCv;

    k_init_prep<<<64, 256>>>(We);                    // 16384 threads: covers NN and 32*256
    k_count<<<(EE + 255) / 256, 256>>>(ei);
    k_scan<<<1, 1024>>>();
    k_fill<<<(EE + 255) / 256, 256>>>(ei);

    dim3 pg((NN + 63) / 64, 4);
    k_proj2<<<pg, 256>>>(x, Wl, bl, Wr, br);

    k_loopattr<<<(NN + 7) / 8, 256>>>(eattr);

    k_logits_mma<<<(TOT + 63) / 64, 256>>>(ei, eattr, att);

    k_node<<<NN, 256>>>(ei, bias, gamma, beta, out_h, out_alpha);
}

// round 8
// speedup vs baseline: 1.9038x; 1.0519x over previous
#include <cuda_runtime.h>
#include <cuda_fp16.h>
#include <cstdint>

#define NN 10000
#define EE 320000
#define HCv 256
#define EDv 64
#define TOT (EE + NN)
#define FULLMASK 0xffffffffu

static __device__ __forceinline__ int clampN(int v) {
    v = v < 0 ? 0 : v;
    return v > (NN - 1) ? (NN - 1) : v;
}

static __device__ __forceinline__ uint32_t pack_h2(float x, float y) {
    __half2 h = __floats2half2_rn(x, y);
    return *(uint32_t*)&h;
}

// ---------------- scratch (device globals; no allocations allowed) ----------------
static __device__ float    g_xl[NN * HCv];
static __device__ float    g_xr[NN * HCv];
static __device__ float    g_logits[TOT * 4];
static __device__ float    g_loop_attr[NN * EDv];
static __device__ uint32_t g_WeB_hi[32 * HCv];        // We: [k-pair][col] packed half2
static __device__ uint32_t g_WeB_lo[32 * HCv];
static __device__ uint32_t g_WB_hi[2 * 128 * HCv];    // Wl,Wr: [w][k-pair][col] packed half2
static __device__ uint32_t g_WB_lo[2 * 128 * HCv];
static __device__ int      g_deg[NN];
static __device__ int      g_rowptr[NN + 1];
static __device__ int      g_cursor[NN];
static __device__ int      g_eids[EE];

// ---------------- CSR init + weight fp16 hi/lo packing (merged) ----------------
__global__ void k_init_prep(const float* __restrict__ We, const float* __restrict__ Wl,
                            const float* __restrict__ Wr) {
    int i = blockIdx.x * blockDim.x + threadIdx.x;   // 65536 threads
    if (i < NN) { g_deg[i] = 0; g_cursor[i] = 0; }
    if (i < 32 * HCv) {                               // We: K=64 -> 32 k-pairs
        int c = i & 255, k2 = i >> 8;
        float v0 = We[c * 64 + 2 * k2];
        float v1 = We[c * 64 + 2 * k2 + 1];
        __half h0 = __float2half_rn(v0), h1 = __float2half_rn(v1);
        g_WeB_hi[k2 * 256 + c] = pack_h2(__half2float(h0), __half2float(h1));
        g_WeB_lo[k2 * 256 + c] = pack_h2(v0 - __half2float(h0), v1 - __half2float(h1));
    }
    if (i < 2 * 128 * HCv) {                          // Wl/Wr: K=256 -> 128 k-pairs
        int w = i >> 15;
        int rem = i & 32767;
        int c = rem & 255, k2 = rem >> 8;
        const float* W = w ? Wr : Wl;
        float v0 = W[c * 256 + 2 * k2];
        float v1 = W[c * 256 + 2 * k2 + 1];
        __half h0 = __float2half_rn(v0), h1 = __float2half_rn(v1);
        g_WB_hi[i] = pack_h2(__half2float(h0), __half2float(h1));
        g_WB_lo[i] = pack_h2(v0 - __half2float(h0), v1 - __half2float(h1));
    }
}

__global__ void k_count(const int* __restrict__ ei) {
    int e = blockIdx.x * blockDim.x + threadIdx.x;
    if (e < EE) atomicAdd(&g_deg[clampN(ei[EE + e])], 1);
}

// 1024 threads; each scans 10 elements serially, then one 1024-wide scan.
__global__ void k_scan() {
    __shared__ int part[1024];
    int t = threadIdx.x;
    int base = t * 10;
    int pre[10];
    int s = 0;
#pragma unroll
    for (int j = 0; j < 10; j++) {
        int idx = base + j;
        int v = (idx < NN) ? g_deg[idx] : 0;
        pre[j] = s;
        s += v;
    }
    part[t] = s;
    __syncthreads();
    for (int off = 1; off < 1024; off <<= 1) {
        int y = (t >= off) ? part[t - off] : 0;
        __syncthreads();
        part[t] += y;
        __syncthreads();
    }
    int excl = (t == 0) ? 0 : part[t - 1];
#pragma unroll
    for (int j = 0; j < 10; j++) {
        int idx = base + j;
        if (idx < NN) g_rowptr[idx] = excl + pre[j];
    }
    if (t == 1023) g_rowptr[NN] = excl + s;
}

__global__ void k_fill(const int* __restrict__ ei) {
    int e = blockIdx.x * blockDim.x + threadIdx.x;
    if (e < EE) {
        int d = clampN(ei[EE + e]);
        int pos = g_rowptr[d] + atomicAdd(&g_cursor[d], 1);
        if (pos >= 0 && pos < EE) g_eids[pos] = e;
    }
}

// ---------------- node projections via split-fp16 mma ----------------
// 64 nodes/block, 8 warps = 4 M-tiles x 2 N-groups (128 cols). Loop w in {Wl,Wr}.
#define XS 17     // X chunk row stride
#define BS2 264   // B row stride (uint32 half2)

__global__ __launch_bounds__(256) void k_proj_mma(const float* __restrict__ X,
                                                  const float* __restrict__ bl,
                                                  const float* __restrict__ br) {
    __shared__ float    Xs[64 * XS];       // 4.25 KB (one k16 chunk)
    __shared__ uint32_t WB_h[8 * BS2];     // 8.45 KB
    __shared__ uint32_t WB_l[8 * BS2];

    int t = threadIdx.x;
    int lane = t & 31;
    int warp = t >> 5;
    int mt = warp >> 1;
    int ng = warp & 1;
    int grp = lane >> 2;
    int thr = lane & 3;
    int row0 = mt * 16 + grp;
    int bm = blockIdx.x * 64;

#pragma unroll
    for (int w = 0; w < 2; w++) {
        const uint32_t* Whi = g_WB_hi + w * 32768;
        const uint32_t* Wlo = g_WB_lo + w * 32768;
        float acc[16][4];
#pragma unroll
        for (int nt = 0; nt < 16; nt++)
#pragma unroll
            for (int q = 0; q < 4; q++) acc[nt][q] = 0.f;

        for (int kc = 0; kc < 16; kc++) {
            __syncthreads();
            // stage X chunk 64 x 16 (fp32)
#pragma unroll
            for (int r = 0; r < 4; r++) {
                int i = t + r * 256;
                int row = i >> 4, col = i & 15;
                int gr = bm + row;
                Xs[row * XS + col] = (gr < NN) ? X[(size_t)gr * 256 + kc * 16 + col] : 0.f;
            }
            // stage W chunk: 8 k-pairs x 256 cols (hi & lo)
#pragma unroll
            for (int r = 0; r < 8; r++) {
                int i = t + r * 256;
                int kk = i >> 8, c = i & 255;
                WB_h[kk * BS2 + c] = Whi[(kc * 8 + kk) * 256 + c];
                WB_l[kk * BS2 + c] = Wlo[(kc * 8 + kk) * 256 + c];
            }
            __syncthreads();

            int cA = thr * 2;
            float x00 = Xs[row0 * XS + cA],           x01 = Xs[row0 * XS + cA + 1];
            float x10 = Xs[(row0 + 8) * XS + cA],     x11 = Xs[(row0 + 8) * XS + cA + 1];
            float x20 = Xs[row0 * XS + cA + 8],       x21 = Xs[row0 * XS + cA + 9];
            float x30 = Xs[(row0 + 8) * XS + cA + 8], x31 = Xs[(row0 + 8) * XS + cA + 9];
            __half h00 = __float2half_rn(x00), h01 = __float2half_rn(x01);
            __half h10 = __float2half_rn(x10), h11 = __float2half_rn(x11);
            __half h20 = __float2half_rn(x20), h21 = __float2half_rn(x21);
            __half h30 = __float2half_rn(x30), h31 = __float2half_rn(x31);
            uint32_t ah0 = pack_h2(__half2float(h00), __half2float(h01));
            uint32_t ah1 = pack_h2(__half2float(h10), __half2float(h11));
            uint32_t ah2 = pack_h2(__half2float(h20), __half2float(h21));
            uint32_t ah3 = pack_h2(__half2float(h30), __half2float(h31));
            uint32_t al0 = pack_h2(x00 - __half2float(h00), x01 - __half2float(h01));
            uint32_t al1 = pack_h2(x10 - __half2float(h10), x11 - __half2float(h11));
            uint32_t al2 = pack_h2(x20 - __half2float(h20), x21 - __half2float(h21));
            uint32_t al3 = pack_h2(x30 - __half2float(h30), x31 - __half2float(h31));

#pragma unroll
            for (int nt = 0; nt < 16; nt++) {
                int ccol = ng * 128 + nt * 8 + grp;
                uint32_t bh0 = WB_h[thr * BS2 + ccol];
                uint32_t bh1 = WB_h[(thr + 4) * BS2 + ccol];
                uint32_t bl0 = WB_l[thr * BS2 + ccol];
                uint32_t bl1 = WB_l[(thr + 4) * BS2 + ccol];
                asm("mma.sync.aligned.m16n8k16.row.col.f32.f16.f16.f32 "
                    "{%0,%1,%2,%3}, {%4,%5,%6,%7}, {%8,%9}, {%0,%1,%2,%3};"
                    : "+f"(acc[nt][0]), "+f"(acc[nt][1]), "+f"(acc[nt][2]), "+f"(acc[nt][3])
                    : "r"(al0), "r"(al1), "r"(al2), "r"(al3), "r"(bh0), "r"(bh1));
                asm("mma.sync.aligned.m16n8k16.row.col.f32.f16.f16.f32 "
                    "{%0,%1,%2,%3}, {%4,%5,%6,%7}, {%8,%9}, {%0,%1,%2,%3};"
                    : "+f"(acc[nt][0]), "+f"(acc[nt][1]), "+f"(acc[nt][2]), "+f"(acc[nt][3])
                    : "r"(ah0), "r"(ah1), "r"(ah2), "r"(ah3), "r"(bl0), "r"(bl1));
                asm("mma.sync.aligned.m16n8k16.row.col.f32.f16.f16.f32 "
                    "{%0,%1,%2,%3}, {%4,%5,%6,%7}, {%8,%9}, {%0,%1,%2,%3};"
                    : "+f"(acc[nt][0]), "+f"(acc[nt][1]), "+f"(acc[nt][2]), "+f"(acc[nt][3])
                    : "r"(ah0), "r"(ah1), "r"(ah2), "r"(ah3), "r"(bh0), "r"(bh1));
            }
        }

        // epilogue: direct global stores + bias
        float* out = w ? g_xr : g_xl;
        const float* bb = w ? br : bl;
        int r0 = bm + row0, r1 = bm + row0 + 8;
#pragma unroll
        for (int nt = 0; nt < 16; nt++) {
            int col = ng * 128 + nt * 8 + 2 * thr;
            if (r0 < NN) {
                out[(size_t)r0 * 256 + col]     = acc[nt][0] + bb[col];
                out[(size_t)r0 * 256 + col + 1] = acc[nt][1] + bb[col + 1];
            }
            if (r1 < NN) {
                out[(size_t)r1 * 256 + col]     = acc[nt][2] + bb[col];
                out[(size_t)r1 * 256 + col + 1] = acc[nt][3] + bb[col + 1];
            }
        }
        __syncthreads();
    }
}

// ---------------- self-loop attr = mean of incoming edge_attr ----------------
__global__ void k_loopattr(const float* __restrict__ ea) {
    int w = blockIdx.x * (blockDim.x >> 5) + (threadIdx.x >> 5);
    int lane = threadIdx.x & 31;
    if (w >= NN) return;
    int start = g_rowptr[w];
    int deg = g_rowptr[w + 1] - start;
    float a0 = 0.f, a1 = 0.f;
    for (int i = 0; i < deg; i++) {
        int e = g_eids[start + i];
        a0 += ea[(size_t)e * 64 + lane];
        a1 += ea[(size_t)e * 64 + 32 + lane];
    }
    float inv = 1.0f / (float)max(deg, 1);
    g_loop_attr[w * 64 + lane] = a0 * inv;
    g_loop_attr[w * 64 + 32 + lane] = a1 * inv;
}

// ---------------- edge logits via split-fp16 m16n8k16 mma, 64 edges/block ----------------
#define EAS 72
#define EPS 68

__global__ __launch_bounds__(256) void k_logits_mma(const int* __restrict__ ei,
                                                    const float* __restrict__ eattr,
                                                    const float* __restrict__ att) {
    __shared__ float    EA_s[64 * EAS];
    __shared__ uint32_t B_hi[8 * BS2];
    __shared__ uint32_t B_lo[8 * BS2];
    __shared__ float    EP_s[64 * EPS];
    __shared__ float    att_s[256];
    __shared__ int      s_src[64], s_dst[64];

    int t = threadIdx.x;
    int lane = t & 31;
    int warp = t >> 5;
    int mt = warp >> 1;
    int ng = warp & 1;

    att_s[t] = att[t];

    int base = blockIdx.x * 64;
    if (base > TOT - 64) base = TOT - 64;

    if (t < 64) {
        int e = base + t;
        int s, d;
        if (e < EE) { s = clampN(ei[e]); d = clampN(ei[EE + e]); }
        else { s = e - EE; d = e - EE; }
        s_src[t] = s; s_dst[t] = d;
    }
    {
        int el = t >> 2, part = t & 3;
        int e = base + el;
        const float* p = (e < EE) ? (eattr + (size_t)e * 64) : (g_loop_attr + (size_t)(e - EE) * 64);
        float* q = &EA_s[el * EAS + part * 16];
#pragma unroll
        for (int r = 0; r < 4; r++)
            *(float4*)(q + r * 4) = *(const float4*)&p[part * 16 + r * 4];
    }

    int grp = lane >> 2;
    int thr = lane & 3;
    int row0 = mt * 16 + grp;

    float acc[4][4][4];
#pragma unroll
    for (int qq = 0; qq < 4; qq++)
#pragma unroll
        for (int nt = 0; nt < 4; nt++)
#pragma unroll
            for (int q = 0; q < 4; q++) acc[qq][nt][q] = 0.f;

    __syncthreads();

    for (int kc = 0; kc < 4; kc++) {
        if (kc) __syncthreads();
#pragma unroll
        for (int r = 0; r < 8; r++) {
            int i = t + r * 256;
            int kk = i >> 8, c = i & 255;
            int gidx = (kc * 8 + kk) * 256 + c;
            B_hi[kk * BS2 + c] = g_WeB_hi[gidx];
            B_lo[kk * BS2 + c] = g_WeB_lo[gidx];
        }
        __syncthreads();

        int cA = kc * 16 + thr * 2;
        float x00 = EA_s[row0 * EAS + cA],           x01 = EA_s[row0 * EAS + cA + 1];
        float x10 = EA_s[(row0 + 8) * EAS + cA],     x11 = EA_s[(row0 + 8) * EAS + cA + 1];
        float x20 = EA_s[row0 * EAS + cA + 8],       x21 = EA_s[row0 * EAS + cA + 9];
        float x30 = EA_s[(row0 + 8) * EAS + cA + 8], x31 = EA_s[(row0 + 8) * EAS + cA + 9];
        __half h00 = __float2half_rn(x00), h01 = __float2half_rn(x01);
        __half h10 = __float2half_rn(x10), h11 = __float2half_rn(x11);
        __half h20 = __float2half_rn(x20), h21 = __float2half_rn(x21);
        __half h30 = __float2half_rn(x30), h31 = __float2half_rn(x31);
        uint32_t ah0 = pack_h2(__half2float(h00), __half2float(h01));
        uint32_t ah1 = pack_h2(__half2float(h10), __half2float(h11));
        uint32_t ah2 = pack_h2(__half2float(h20), __half2float(h21));
        uint32_t ah3 = pack_h2(__half2float(h30), __half2float(h31));
        uint32_t al0 = pack_h2(x00 - __half2float(h00), x01 - __half2float(h01));
        uint32_t al1 = pack_h2(x10 - __half2float(h10), x11 - __half2float(h11));
        uint32_t al2 = pack_h2(x20 - __half2float(h20), x21 - __half2float(h21));
        uint32_t al3 = pack_h2(x30 - __half2float(h30), x31 - __half2float(h31));

#pragma unroll
        for (int qq = 0; qq < 4; qq++) {
#pragma unroll
            for (int nt = 0; nt < 4; nt++) {
                int ccol = qq * 64 + ng * 32 + nt * 8 + grp;
                uint32_t bh0 = B_hi[thr * BS2 + ccol];
                uint32_t bh1 = B_hi[(thr + 4) * BS2 + ccol];
                uint32_t bl0 = B_lo[thr * BS2 + ccol];
                uint32_t bl1 = B_lo[(thr + 4) * BS2 + ccol];
                asm("mma.sync.aligned.m16n8k16.row.col.f32.f16.f16.f32 "
                    "{%0,%1,%2,%3}, {%4,%5,%6,%7}, {%8,%9}, {%0,%1,%2,%3};"
                    : "+f"(acc[qq][nt][0]), "+f"(acc[qq][nt][1]), "+f"(acc[qq][nt][2]), "+f"(acc[qq][nt][3])
                    : "r"(al0), "r"(al1), "r"(al2), "r"(al3), "r"(bh0), "r"(bh1));
                asm("mma.sync.aligned.m16n8k16.row.col.f32.f16.f16.f32 "
                    "{%0,%1,%2,%3}, {%4,%5,%6,%7}, {%8,%9}, {%0,%1,%2,%3};"
                    : "+f"(acc[qq][nt][0]), "+f"(acc[qq][nt][1]), "+f"(acc[qq][nt][2]), "+f"(acc[qq][nt][3])
                    : "r"(ah0), "r"(ah1), "r"(ah2), "r"(ah3), "r"(bl0), "r"(bl1));
                asm("mma.sync.aligned.m16n8k16.row.col.f32.f16.f16.f32 "
                    "{%0,%1,%2,%3}, {%4,%5,%6,%7}, {%8,%9}, {%0,%1,%2,%3};"
                    : "+f"(acc[qq][nt][0]), "+f"(acc[qq][nt][1]), "+f"(acc[qq][nt][2]), "+f"(acc[qq][nt][3])
                    : "r"(ah0), "r"(ah1), "r"(ah2), "r"(ah3), "r"(bh0), "r"(bh1));
            }
        }
    }

#pragma unroll
    for (int quarter = 0; quarter < 4; quarter++) {
        __syncthreads();
#pragma unroll
        for (int nt = 0; nt < 4; nt++) {
            int cb = ng * 32 + nt * 8 + 2 * thr;
            EP_s[row0 * EPS + cb]           = acc[quarter][nt][0];
            EP_s[row0 * EPS + cb + 1]       = acc[quarter][nt][1];
            EP_s[(row0 + 8) * EPS + cb]     = acc[quarter][nt][2];
            EP_s[(row0 + 8) * EPS + cb + 1] = acc[quarter][nt][3];
        }
        __syncthreads();
        {
            int el = t >> 2, sub = t & 3;
            int c0 = sub * 16;
            int src = s_src[el], dst = s_dst[el];
            const float* xlp = g_xl + (size_t)src * 256 + quarter * 64 + c0;
            const float* xrp = g_xr + (size_t)dst * 256 + quarter * 64 + c0;
            const float* epp = &EP_s[el * EPS + c0];
            const float* ats = &att_s[quarter * 64 + c0];
            float s = 0.f;
#pragma unroll
            for (int q4 = 0; q4 < 4; q4++) {
                float4 ev = *(const float4*)&epp[q4 * 4];
                float4 lv = *(const float4*)&xlp[q4 * 4];
                float4 rv = *(const float4*)&xrp[q4 * 4];
                float4 av = *(const float4*)&ats[q4 * 4];
                float m0 = ev.x + lv.x + rv.x; m0 = (m0 >= 0.f) ? m0 : 0.2f * m0;
                float m1 = ev.y + lv.y + rv.y; m1 = (m1 >= 0.f) ? m1 : 0.2f * m1;
                float m2 = ev.z + lv.z + rv.z; m2 = (m2 >= 0.f) ? m2 : 0.2f * m2;
                float m3 = ev.w + lv.w + rv.w; m3 = (m3 >= 0.f) ? m3 : 0.2f * m3;
                s = fmaf(m0, av.x, s); s = fmaf(m1, av.y, s);
                s = fmaf(m2, av.z, s); s = fmaf(m3, av.w, s);
            }
            s += __shfl_xor_sync(FULLMASK, s, 1);
            s += __shfl_xor_sync(FULLMASK, s, 2);
            if (sub == 0)
                g_logits[(size_t)(base + el) * 4 + quarter] = s;
        }
    }
}

// ---------------- per-node softmax + aggregation + SiLU + LayerNorm + alpha out ----------------
__global__ void k_node(const int* __restrict__ ei, const float* __restrict__ bias,
                       const float* __restrict__ gamma, const float* __restrict__ beta,
                       float* __restrict__ out_h, float* __restrict__ out_alpha) {
    __shared__ float red[256];
    __shared__ float s_mx[4];
    __shared__ float s_inv[4];
    __shared__ float s_alpha[64 * 4];
    __shared__ int   s_srcs[64];
    __shared__ float s_mu, s_var;
    int n = blockIdx.x, t = threadIdx.x;
    int start = g_rowptr[n];
    int deg = g_rowptr[n + 1] - start;
    int cnt = deg + 1;
    int h4 = t & 3;

    float lm = -1e30f;
    for (int i = t >> 2; i < cnt; i += 64) {
        int e = (i < deg) ? g_eids[start + i] : (EE + n);
        lm = fmaxf(lm, g_logits[(size_t)e * 4 + h4]);
    }
    red[t] = lm;
    __syncthreads();
    if (t < 4) {
        float m = -1e30f;
        for (int j = t; j < 256; j += 4) m = fmaxf(m, red[j]);
        s_mx[t] = m;
    }
    __syncthreads();
    float mxh = s_mx[h4];
    float ls = 0.f;
    for (int i = t >> 2; i < cnt; i += 64) {
        int e = (i < deg) ? g_eids[start + i] : (EE + n);
        ls += __expf(g_logits[(size_t)e * 4 + h4] - mxh);
    }
    red[t] = ls;
    __syncthreads();
    if (t < 4) {
        float sum = 0.f;
        for (int j = t; j < 256; j += 4) sum += red[j];
        s_inv[t] = 1.0f / sum;
    }
    __syncthreads();

    int c = t, hh = c >> 6;
    float acc = 0.f;
    for (int bb = 0; bb < cnt; bb += 64) {
        int m = min(64, cnt - bb);
        __syncthreads();
        if (t < m) {
            int i = bb + t;
            int e = (i < deg) ? g_eids[start + i] : (EE + n);
            s_srcs[t] = (e < EE) ? clampN(ei[e]) : n;
            float4 lg = *(const float4*)&g_logits[(size_t)e * 4];
            float a0 = __expf(lg.x - s_mx[0]) * s_inv[0];
            float a1 = __expf(lg.y - s_mx[1]) * s_inv[1];
            float a2 = __expf(lg.z - s_mx[2]) * s_inv[2];
            float a3 = __expf(lg.w - s_mx[3]) * s_inv[3];
            s_alpha[t * 4 + 0] = a0;
            s_alpha[t * 4 + 1] = a1;
            s_alpha[t * 4 + 2] = a2;
            s_alpha[t * 4 + 3] = a3;
            *(float4*)&out_alpha[(size_t)e * 4] = make_float4(a0, a1, a2, a3);
        }
        __syncthreads();
        for (int i = 0; i < m; i++)
            acc = fmaf(s_alpha[i * 4 + hh], g_xl[(size_t)s_srcs[i] * 256 + c], acc);
    }

    float v = acc + bias[c];
    v = v / (1.0f + __expf(-v));   // SiLU
    __syncthreads();
    red[t] = v;
    __syncthreads();
    for (int s = 128; s > 0; s >>= 1) { if (t < s) red[t] += red[t + s]; __syncthreads(); }
    if (t == 0) s_mu = red[0] * (1.0f / 256.0f);
    __syncthreads();
    float d = v - s_mu;
    red[t] = d * d;
    __syncthreads();
    for (int s = 128; s > 0; s >>= 1) { if (t < s) red[t] += red[t + s]; __syncthreads(); }
    if (t == 0) s_var = red[0] * (1.0f / 256.0f);
    __syncthreads();
    out_h[(size_t)n * 256 + c] = d * rsqrtf(s_var + 1e-5f) * gamma[c] + beta[c];
}

// ---------------- launch (kernel launches ONLY — graph-capturable) ----------------
extern "C" void kernel_launch(void* const* d_in, const int* in_sizes, int n_in,
                              void* d_out, int out_size) {
    const float* x     = (const float*)d_in[0];
    const int*   ei    = (const int*)d_in[1];     // int32 (JAX x64-disabled)
    const float* eattr = (const float*)d_in[2];
    const float* Wl    = (const float*)d_in[3];
    const float* bl    = (const float*)d_in[4];
    const float* Wr    = (const float*)d_in[5];
    const float* br    = (const float*)d_in[6];
    const float* We    = (const float*)d_in[7];
    const float* att   = (const float*)d_in[8];
    const float* bias  = (const float*)d_in[9];
    const float* gamma = (const float*)d_in[10];
    const float* beta  = (const float*)d_in[11];

    float* out_h = (float*)d_out;
    float* out_alpha = out_h + (size_t)NN * HCv;

    k_init_prep<<<256, 256>>>(We, Wl, Wr);          // 65536 threads
    k_count<<<(EE + 255) / 256, 256>>>(ei);
    k_scan<<<1, 1024>>>();
    k_fill<<<(EE + 255) / 256, 256>>>(ei);

    k_proj_mma<<<(NN + 63) / 64, 256>>>(x, bl, br);

    k_loopattr<<<(NN + 7) / 8, 256>>>(eattr);

    k_logits_mma<<<(TOT + 63) / 64, 256>>>(ei, eattr, att);

    k_node<<<NN, 256>>>(ei, bias, gamma, beta, out_h, out_alpha);
}

// round 9
// speedup vs baseline: 1.9338x; 1.0158x over previous
#include <cuda_runtime.h>
#include <cuda_fp16.h>
#include <cstdint>

#define NN 10000
#define EE 320000
#define HCv 256
#define EDv 64
#define TOT (EE + NN)
#define FULLMASK 0xffffffffu

static __device__ __forceinline__ int clampN(int v) {
    v = v < 0 ? 0 : v;
    return v > (NN - 1) ? (NN - 1) : v;
}

static __device__ __forceinline__ uint32_t pack_h2(float x, float y) {
    __half2 h = __floats2half2_rn(x, y);
    return *(uint32_t*)&h;
}

// ---------------- scratch (device globals; no allocations allowed) ----------------
static __device__ float    g_xl[NN * HCv];
static __device__ float    g_xr[NN * HCv];
static __device__ float    g_logits[TOT * 4];         // indexed by CSR position
static __device__ float    g_loop_attr[NN * EDv];
static __device__ uint32_t g_WeB_hi[32 * HCv];
static __device__ uint32_t g_WeB_lo[32 * HCv];
static __device__ uint32_t g_WB_hi[2 * 128 * HCv];
static __device__ uint32_t g_WB_lo[2 * 128 * HCv];
static __device__ int      g_deg[NN];
static __device__ int      g_rowptr[NN + 1];
static __device__ int      g_cursor[NN];
static __device__ int      g_eids[EE];                // CSR pos -> original edge id
static __device__ int      g_esrc[EE];                // CSR pos -> src node
static __device__ int      g_edst[EE];                // CSR pos -> dst node

// ---------------- CSR init + weight fp16 hi/lo packing (merged) ----------------
__global__ void k_init_prep(const float* __restrict__ We, const float* __restrict__ Wl,
                            const float* __restrict__ Wr) {
    int i = blockIdx.x * blockDim.x + threadIdx.x;   // 65536 threads
    if (i < NN) { g_deg[i] = 0; g_cursor[i] = 0; }
    if (i < 32 * HCv) {
        int c = i & 255, k2 = i >> 8;
        float v0 = We[c * 64 + 2 * k2];
        float v1 = We[c * 64 + 2 * k2 + 1];
        __half h0 = __float2half_rn(v0), h1 = __float2half_rn(v1);
        g_WeB_hi[k2 * 256 + c] = pack_h2(__half2float(h0), __half2float(h1));
        g_WeB_lo[k2 * 256 + c] = pack_h2(v0 - __half2float(h0), v1 - __half2float(h1));
    }
    if (i < 2 * 128 * HCv) {
        int w = i >> 15;
        int rem = i & 32767;
        int c = rem & 255, k2 = rem >> 8;
        const float* W = w ? Wr : Wl;
        float v0 = W[c * 256 + 2 * k2];
        float v1 = W[c * 256 + 2 * k2 + 1];
        __half h0 = __float2half_rn(v0), h1 = __float2half_rn(v1);
        g_WB_hi[i] = pack_h2(__half2float(h0), __half2float(h1));
        g_WB_lo[i] = pack_h2(v0 - __half2float(h0), v1 - __half2float(h1));
    }
}

__global__ void k_count(const int* __restrict__ ei) {
    int e = blockIdx.x * blockDim.x + threadIdx.x;
    if (e < EE) atomicAdd(&g_deg[clampN(ei[EE + e])], 1);
}

// 1024 threads; each scans 10 elements serially, then one 1024-wide scan.
__global__ void k_scan() {
    __shared__ int part[1024];
    int t = threadIdx.x;
    int base = t * 10;
    int pre[10];
    int s = 0;
#pragma unroll
    for (int j = 0; j < 10; j++) {
        int idx = base + j;
        int v = (idx < NN) ? g_deg[idx] : 0;
        pre[j] = s;
        s += v;
    }
    part[t] = s;
    __syncthreads();
    for (int off = 1; off < 1024; off <<= 1) {
        int y = (t >= off) ? part[t - off] : 0;
        __syncthreads();
        part[t] += y;
        __syncthreads();
    }
    int excl = (t == 0) ? 0 : part[t - 1];
#pragma unroll
    for (int j = 0; j < 10; j++) {
        int idx = base + j;
        if (idx < NN) g_rowptr[idx] = excl + pre[j];
    }
    if (t == 1023) g_rowptr[NN] = excl + s;
}

__global__ void k_fill(const int* __restrict__ ei) {
    int e = blockIdx.x * blockDim.x + threadIdx.x;
    if (e < EE) {
        int d = clampN(ei[EE + e]);
        int pos = g_rowptr[d] + atomicAdd(&g_cursor[d], 1);
        if (pos >= 0 && pos < EE) {
            g_eids[pos] = e;
            g_esrc[pos] = clampN(ei[e]);
            g_edst[pos] = d;
        }
    }
}

// ---------------- node projections via split-fp16 mma ----------------
#define XS 17
#define BS2 264

__global__ __launch_bounds__(256) void k_proj_mma(const float* __restrict__ X,
                                                  const float* __restrict__ bl,
                                                  const float* __restrict__ br) {
    __shared__ float    Xs[64 * XS];
    __shared__ uint32_t WB_h[8 * BS2];
    __shared__ uint32_t WB_l[8 * BS2];

    int t = threadIdx.x;
    int lane = t & 31;
    int warp = t >> 5;
    int mt = warp >> 1;
    int ng = warp & 1;
    int grp = lane >> 2;
    int thr = lane & 3;
    int row0 = mt * 16 + grp;
    int bm = blockIdx.x * 64;

#pragma unroll
    for (int w = 0; w < 2; w++) {
        const uint32_t* Whi = g_WB_hi + w * 32768;
        const uint32_t* Wlo = g_WB_lo + w * 32768;
        float acc[16][4];
#pragma unroll
        for (int nt = 0; nt < 16; nt++)
#pragma unroll
            for (int q = 0; q < 4; q++) acc[nt][q] = 0.f;

        for (int kc = 0; kc < 16; kc++) {
            __syncthreads();
#pragma unroll
            for (int r = 0; r < 4; r++) {
                int i = t + r * 256;
                int row = i >> 4, col = i & 15;
                int gr = bm + row;
                Xs[row * XS + col] = (gr < NN) ? X[(size_t)gr * 256 + kc * 16 + col] : 0.f;
            }
#pragma unroll
            for (int r = 0; r < 8; r++) {
                int i = t + r * 256;
                int kk = i >> 8, c = i & 255;
                WB_h[kk * BS2 + c] = Whi[(kc * 8 + kk) * 256 + c];
                WB_l[kk * BS2 + c] = Wlo[(kc * 8 + kk) * 256 + c];
            }
            __syncthreads();

            int cA = thr * 2;
            float x00 = Xs[row0 * XS + cA],           x01 = Xs[row0 * XS + cA + 1];
            float x10 = Xs[(row0 + 8) * XS + cA],     x11 = Xs[(row0 + 8) * XS + cA + 1];
            float x20 = Xs[row0 * XS + cA + 8],       x21 = Xs[row0 * XS + cA + 9];
            float x30 = Xs[(row0 + 8) * XS + cA + 8], x31 = Xs[(row0 + 8) * XS + cA + 9];
            __half h00 = __float2half_rn(x00), h01 = __float2half_rn(x01);
            __half h10 = __float2half_rn(x10), h11 = __float2half_rn(x11);
            __half h20 = __float2half_rn(x20), h21 = __float2half_rn(x21);
            __half h30 = __float2half_rn(x30), h31 = __float2half_rn(x31);
            uint32_t ah0 = pack_h2(__half2float(h00), __half2float(h01));
            uint32_t ah1 = pack_h2(__half2float(h10), __half2float(h11));
            uint32_t ah2 = pack_h2(__half2float(h20), __half2float(h21));
            uint32_t ah3 = pack_h2(__half2float(h30), __half2float(h31));
            uint32_t al0 = pack_h2(x00 - __half2float(h00), x01 - __half2float(h01));
            uint32_t al1 = pack_h2(x10 - __half2float(h10), x11 - __half2float(h11));
            uint32_t al2 = pack_h2(x20 - __half2float(h20), x21 - __half2float(h21));
            uint32_t al3 = pack_h2(x30 - __half2float(h30), x31 - __half2float(h31));

#pragma unroll
            for (int nt = 0; nt < 16; nt++) {
                int ccol = ng * 128 + nt * 8 + grp;
                uint32_t bh0 = WB_h[thr * BS2 + ccol];
                uint32_t bh1 = WB_h[(thr + 4) * BS2 + ccol];
                uint32_t bl0 = WB_l[thr * BS2 + ccol];
                uint32_t bl1 = WB_l[(thr + 4) * BS2 + ccol];
                asm("mma.sync.aligned.m16n8k16.row.col.f32.f16.f16.f32 "
                    "{%0,%1,%2,%3}, {%4,%5,%6,%7}, {%8,%9}, {%0,%1,%2,%3};"
                    : "+f"(acc[nt][0]), "+f"(acc[nt][1]), "+f"(acc[nt][2]), "+f"(acc[nt][3])
                    : "r"(al0), "r"(al1), "r"(al2), "r"(al3), "r"(bh0), "r"(bh1));
                asm("mma.sync.aligned.m16n8k16.row.col.f32.f16.f16.f32 "
                    "{%0,%1,%2,%3}, {%4,%5,%6,%7}, {%8,%9}, {%0,%1,%2,%3};"
                    : "+f"(acc[nt][0]), "+f"(acc[nt][1]), "+f"(acc[nt][2]), "+f"(acc[nt][3])
                    : "r"(ah0), "r"(ah1), "r"(ah2), "r"(ah3), "r"(bl0), "r"(bl1));
                asm("mma.sync.aligned.m16n8k16.row.col.f32.f16.f16.f32 "
                    "{%0,%1,%2,%3}, {%4,%5,%6,%7}, {%8,%9}, {%0,%1,%2,%3};"
                    : "+f"(acc[nt][0]), "+f"(acc[nt][1]), "+f"(acc[nt][2]), "+f"(acc[nt][3])
                    : "r"(ah0), "r"(ah1), "r"(ah2), "r"(ah3), "r"(bh0), "r"(bh1));
            }
        }

        float* out = w ? g_xr : g_xl;
        const float* bb = w ? br : bl;
        int r0 = bm + row0, r1 = bm + row0 + 8;
#pragma unroll
        for (int nt = 0; nt < 16; nt++) {
            int col = ng * 128 + nt * 8 + 2 * thr;
            if (r0 < NN) {
                out[(size_t)r0 * 256 + col]     = acc[nt][0] + bb[col];
                out[(size_t)r0 * 256 + col + 1] = acc[nt][1] + bb[col + 1];
            }
            if (r1 < NN) {
                out[(size_t)r1 * 256 + col]     = acc[nt][2] + bb[col];
                out[(size_t)r1 * 256 + col + 1] = acc[nt][3] + bb[col + 1];
            }
        }
        __syncthreads();
    }
}

// ---------------- self-loop attr = mean of incoming edge_attr ----------------
__global__ void k_loopattr(const float* __restrict__ ea) {
    int w = blockIdx.x * (blockDim.x >> 5) + (threadIdx.x >> 5);
    int lane = threadIdx.x & 31;
    if (w >= NN) return;
    int start = g_rowptr[w];
    int deg = g_rowptr[w + 1] - start;
    float a0 = 0.f, a1 = 0.f;
    for (int i = 0; i < deg; i++) {
        int e = g_eids[start + i];
        a0 += ea[(size_t)e * 64 + lane];
        a1 += ea[(size_t)e * 64 + 32 + lane];
    }
    float inv = 1.0f / (float)max(deg, 1);
    g_loop_attr[w * 64 + lane] = a0 * inv;
    g_loop_attr[w * 64 + 32 + lane] = a1 * inv;
}

// ---------------- edge logits via split-fp16 mma, CSR-position order ----------------
// Positions p in [0, TOT): p<EE -> CSR edge (dst-sorted), p>=EE -> self loop p-EE.
// Within a block dsts are nearly constant -> xr gathers L1-cached.
// Logits stored BY POSITION -> k_node reads are sequential.
#define EAS 72
#define EPS 68

__global__ __launch_bounds__(256) void k_logits_mma(const float* __restrict__ eattr,
                                                    const float* __restrict__ att) {
    __shared__ float    EA_s[64 * EAS];
    __shared__ uint32_t B_hi[8 * BS2];
    __shared__ uint32_t B_lo[8 * BS2];
    __shared__ float    EP_s[64 * EPS];
    __shared__ float    att_s[256];
    __shared__ int      s_src[64], s_dst[64];

    int t = threadIdx.x;
    int lane = t & 31;
    int warp = t >> 5;
    int mt = warp >> 1;
    int ng = warp & 1;

    att_s[t] = att[t];

    int base = blockIdx.x * 64;
    if (base > TOT - 64) base = TOT - 64;   // tail overlap: identical stores

    if (t < 64) {
        int p = base + t;
        int s, d;
        if (p < EE) { s = g_esrc[p]; d = g_edst[p]; }
        else { s = p - EE; d = p - EE; }
        s_src[t] = s; s_dst[t] = d;
    }
    {
        int el = t >> 2, part = t & 3;
        int p = base + el;
        const float* a;
        if (p < EE) a = eattr + (size_t)g_eids[p] * 64;
        else        a = g_loop_attr + (size_t)(p - EE) * 64;
        float* q = &EA_s[el * EAS + part * 16];
#pragma unroll
        for (int r = 0; r < 4; r++)
            *(float4*)(q + r * 4) = *(const float4*)&a[part * 16 + r * 4];
    }

    int grp = lane >> 2;
    int thr = lane & 3;
    int row0 = mt * 16 + grp;

    float acc[4][4][4];
#pragma unroll
    for (int qq = 0; qq < 4; qq++)
#pragma unroll
        for (int nt = 0; nt < 4; nt++)
#pragma unroll
            for (int q = 0; q < 4; q++) acc[qq][nt][q] = 0.f;

    __syncthreads();

    for (int kc = 0; kc < 4; kc++) {
        if (kc) __syncthreads();
#pragma unroll
        for (int r = 0; r < 8; r++) {
            int i = t + r * 256;
            int kk = i >> 8, c = i & 255;
            int gidx = (kc * 8 + kk) * 256 + c;
            B_hi[kk * BS2 + c] = g_WeB_hi[gidx];
            B_lo[kk * BS2 + c] = g_WeB_lo[gidx];
        }
        __syncthreads();

        int cA = kc * 16 + thr * 2;
        float x00 = EA_s[row0 * EAS + cA],           x01 = EA_s[row0 * EAS + cA + 1];
        float x10 = EA_s[(row0 + 8) * EAS + cA],     x11 = EA_s[(row0 + 8) * EAS + cA + 1];
        float x20 = EA_s[row0 * EAS + cA + 8],       x21 = EA_s[row0 * EAS + cA + 9];
        float x30 = EA_s[(row0 + 8) * EAS + cA + 8], x31 = EA_s[(row0 + 8) * EAS + cA + 9];
        __half h00 = __float2half_rn(x00), h01 = __float2half_rn(x01);
        __half h10 = __float2half_rn(x10), h11 = __float2half_rn(x11);
        __half h20 = __float2half_rn(x20), h21 = __float2half_rn(x21);
        __half h30 = __float2half_rn(x30), h31 = __float2half_rn(x31);
        uint32_t ah0 = pack_h2(__half2float(h00), __half2float(h01));
        uint32_t ah1 = pack_h2(__half2float(h10), __half2float(h11));
        uint32_t ah2 = pack_h2(__half2float(h20), __half2float(h21));
        uint32_t ah3 = pack_h2(__half2float(h30), __half2float(h31));
        uint32_t al0 = pack_h2(x00 - __half2float(h00), x01 - __half2float(h01));
        uint32_t al1 = pack_h2(x10 - __half2float(h10), x11 - __half2float(h11));
        uint32_t al2 = pack_h2(x20 - __half2float(h20), x21 - __half2float(h21));
        uint32_t al3 = pack_h2(x30 - __half2float(h30), x31 - __half2float(h31));

#pragma unroll
        for (int qq = 0; qq < 4; qq++) {
#pragma unroll
            for (int nt = 0; nt < 4; nt++) {
                int ccol = qq * 64 + ng * 32 + nt * 8 + grp;
                uint32_t bh0 = B_hi[thr * BS2 + ccol];
                uint32_t bh1 = B_hi[(thr + 4) * BS2 + ccol];
                uint32_t bl0 = B_lo[thr * BS2 + ccol];
                uint32_t bl1 = B_lo[(thr + 4) * BS2 + ccol];
                asm("mma.sync.aligned.m16n8k16.row.col.f32.f16.f16.f32 "
                    "{%0,%1,%2,%3}, {%4,%5,%6,%7}, {%8,%9}, {%0,%1,%2,%3};"
                    : "+f"(acc[qq][nt][0]), "+f"(acc[qq][nt][1]), "+f"(acc[qq][nt][2]), "+f"(acc[qq][nt][3])
                    : "r"(al0), "r"(al1), "r"(al2), "r"(al3), "r"(bh0), "r"(bh1));
                asm("mma.sync.aligned.m16n8k16.row.col.f32.f16.f16.f32 "
                    "{%0,%1,%2,%3}, {%4,%5,%6,%7}, {%8,%9}, {%0,%1,%2,%3};"
                    : "+f"(acc[qq][nt][0]), "+f"(acc[qq][nt][1]), "+f"(acc[qq][nt][2]), "+f"(acc[qq][nt][3])
                    : "r"(ah0), "r"(ah1), "r"(ah2), "r"(ah3), "r"(bl0), "r"(bl1));
                asm("mma.sync.aligned.m16n8k16.row.col.f32.f16.f16.f32 "
                    "{%0,%1,%2,%3}, {%4,%5,%6,%7}, {%8,%9}, {%0,%1,%2,%3};"
                    : "+f"(acc[qq][nt][0]), "+f"(acc[qq][nt][1]), "+f"(acc[qq][nt][2]), "+f"(acc[qq][nt][3])
                    : "r"(ah0), "r"(ah1), "r"(ah2), "r"(ah3), "r"(bh0), "r"(bh1));
            }
        }
    }

#pragma unroll
    for (int quarter = 0; quarter < 4; quarter++) {
        __syncthreads();
#pragma unroll
        for (int nt = 0; nt < 4; nt++) {
            int cb = ng * 32 + nt * 8 + 2 * thr;
            EP_s[row0 * EPS + cb]           = acc[quarter][nt][0];
            EP_s[row0 * EPS + cb + 1]       = acc[quarter][nt][1];
            EP_s[(row0 + 8) * EPS + cb]     = acc[quarter][nt][2];
            EP_s[(row0 + 8) * EPS + cb + 1] = acc[quarter][nt][3];
        }
        __syncthreads();
        {
            int el = t >> 2, sub = t & 3;
            int c0 = sub * 16;
            int src = s_src[el], dst = s_dst[el];
            const float* xlp = g_xl + (size_t)src * 256 + quarter * 64 + c0;
            const float* xrp = g_xr + (size_t)dst * 256 + quarter * 64 + c0;
            const float* epp = &EP_s[el * EPS + c0];
            const float* ats = &att_s[quarter * 64 + c0];
            float s = 0.f;
#pragma unroll
            for (int q4 = 0; q4 < 4; q4++) {
                float4 ev = *(const float4*)&epp[q4 * 4];
                float4 lv = *(const float4*)&xlp[q4 * 4];
                float4 rv = *(const float4*)&xrp[q4 * 4];
                float4 av = *(const float4*)&ats[q4 * 4];
                float m0 = ev.x + lv.x + rv.x; m0 = (m0 >= 0.f) ? m0 : 0.2f * m0;
                float m1 = ev.y + lv.y + rv.y; m1 = (m1 >= 0.f) ? m1 : 0.2f * m1;
                float m2 = ev.z + lv.z + rv.z; m2 = (m2 >= 0.f) ? m2 : 0.2f * m2;
                float m3 = ev.w + lv.w + rv.w; m3 = (m3 >= 0.f) ? m3 : 0.2f * m3;
                s = fmaf(m0, av.x, s); s = fmaf(m1, av.y, s);
                s = fmaf(m2, av.z, s); s = fmaf(m3, av.w, s);
            }
            s += __shfl_xor_sync(FULLMASK, s, 1);
            s += __shfl_xor_sync(FULLMASK, s, 2);
            if (sub == 0)
                g_logits[(size_t)(base + el) * 4 + quarter] = s;
        }
    }
}

// ---------------- per-node softmax + aggregation + SiLU + LayerNorm + alpha out ----------------
__global__ void k_node(const float* __restrict__ bias,
                       const float* __restrict__ gamma, const float* __restrict__ beta,
                       float* __restrict__ out_h, float* __restrict__ out_alpha) {
    __shared__ float red[256];
    __shared__ float s_mx[4];
    __shared__ float s_inv[4];
    __shared__ float s_alpha[64 * 4];
    __shared__ int   s_srcs[64];
    __shared__ float s_mu, s_var;
    int n = blockIdx.x, t = threadIdx.x;
    int start = g_rowptr[n];
    int deg = g_rowptr[n + 1] - start;
    int cnt = deg + 1;
    int h4 = t & 3;

    float lm = -1e30f;
    for (int i = t >> 2; i < cnt; i += 64) {
        int p = (i < deg) ? (start + i) : (EE + n);
        lm = fmaxf(lm, g_logits[(size_t)p * 4 + h4]);
    }
    red[t] = lm;
    __syncthreads();
    if (t < 4) {
        float m = -1e30f;
        for (int j = t; j < 256; j += 4) m = fmaxf(m, red[j]);
        s_mx[t] = m;
    }
    __syncthreads();
    float mxh = s_mx[h4];
    float ls = 0.f;
    for (int i = t >> 2; i < cnt; i += 64) {
        int p = (i < deg) ? (start + i) : (EE + n);
        ls += __expf(g_logits[(size_t)p * 4 + h4] - mxh);
    }
    red[t] = ls;
    __syncthreads();
    if (t < 4) {
        float sum = 0.f;
        for (int j = t; j < 256; j += 4) sum += red[j];
        s_inv[t] = 1.0f / sum;
    }
    __syncthreads();

    int c = t, hh = c >> 6;
    float acc = 0.f;
    for (int bb = 0; bb < cnt; bb += 64) {
        int m = min(64, cnt - bb);
        __syncthreads();
        if (t < m) {
            int i = bb + t;
            int p = (i < deg) ? (start + i) : (EE + n);
            int e = (i < deg) ? g_eids[p] : (EE + n);
            s_srcs[t] = (i < deg) ? g_esrc[p] : n;
            float4 lg = *(const float4*)&g_logits[(size_t)p * 4];
            float a0 = __expf(lg.x - s_mx[0]) * s_inv[0];
            float a1 = __expf(lg.y - s_mx[1]) * s_inv[1];
            float a2 = __expf(lg.z - s_mx[2]) * s_inv[2];
            float a3 = __expf(lg.w - s_mx[3]) * s_inv[3];
            s_alpha[t * 4 + 0] = a0;
            s_alpha[t * 4 + 1] = a1;
            s_alpha[t * 4 + 2] = a2;
            s_alpha[t * 4 + 3] = a3;
            *(float4*)&out_alpha[(size_t)e * 4] = make_float4(a0, a1, a2, a3);
        }
        __syncthreads();
        for (int i = 0; i < m; i++)
            acc = fmaf(s_alpha[i * 4 + hh], g_xl[(size_t)s_srcs[i] * 256 + c], acc);
    }

    float v = acc + bias[c];
    v = v / (1.0f + __expf(-v));   // SiLU
    __syncthreads();
    red[t] = v;
    __syncthreads();
    for (int s = 128; s > 0; s >>= 1) { if (t < s) red[t] += red[t + s]; __syncthreads(); }
    if (t == 0) s_mu = red[0] * (1.0f / 256.0f);
    __syncthreads();
    float d = v - s_mu;
    red[t] = d * d;
    __syncthreads();
    for (int s = 128; s > 0; s >>= 1) { if (t < s) red[t] += red[t + s]; __syncthreads(); }
    if (t == 0) s_var = red[0] * (1.0f / 256.0f);
    __syncthreads();
    out_h[(size_t)n * 256 + c] = d * rsqrtf(s_var + 1e-5f) * gamma[c] + beta[c];
}

// ---------------- launch (kernel launches ONLY — graph-capturable) ----------------
extern "C" void kernel_launch(void* const* d_in, const int* in_sizes, int n_in,
                              void* d_out, int out_size) {
    const float* x     = (const float*)d_in[0];
    const int*   ei    = (const int*)d_in[1];     // int32 (JAX x64-disabled)
    const float* eattr = (const float*)d_in[2];
    const float* Wl    = (const float*)d_in[3];
    const float* bl    = (const float*)d_in[4];
    const float* Wr    = (const float*)d_in[5];
    const float* br    = (const float*)d_in[6];
    const float* We    = (const float*)d_in[7];
    const float* att   = (const float*)d_in[8];
    const float* bias  = (const float*)d_in[9];
    const float* gamma = (const float*)d_in[10];
    const float* beta  = (const float*)d_in[11];

    float* out_h = (float*)d_out;
    float* out_alpha = out_h + (size_t)NN * HCv;

    k_init_prep<<<256, 256>>>(We, Wl, Wr);
    k_count<<<(EE + 255) / 256, 256>>>(ei);
    k_scan<<<1, 1024>>>();
    k_fill<<<(EE + 255) / 256, 256>>>(ei);

    k_proj_mma<<<(NN + 63) / 64, 256>>>(x, bl, br);

    k_loopattr<<<(NN + 7) / 8, 256>>>(eattr);

    k_logits_mma<<<(TOT + 63) / 64, 256>>>(eattr, att);

    k_node<<<NN, 256>>>(bias, gamma, beta, out_h, out_alpha);
}